// round 8
// baseline (speedup 1.0000x reference)
#include <cuda_runtime.h>
#include <cuda_bf16.h>
#include <math.h>
#include <stdint.h>

// ---------------- problem constants ----------------
#define BB 4
#define SS 2048
#define DD 1024
#define HH 16
#define HSZ 64
#define DFF 4096
#define NROWS (BB * SS)          // 8192
#define QKV_N (3 * DD)           // 3072

// ---------------- scratch (static device globals; no cudaMalloc allowed) ----
__device__ float g_h[NROWS * DD];        // LN output (tf32-rounded)
__device__ float g_qkv[NROWS * QKV_N];   // Q|K|V, head-concat (tf32-rounded)
__device__ float g_wqkv[QKV_N * DD];     // packed qkv weights TRANSPOSED [n][d]
__device__ float g_o[NROWS * DD];        // attention output (tf32-rounded)
__device__ float g_ffh[NROWS * DFF];     // FFN hidden (tf32-rounded)
__device__ float g_wproj[DD * DD];       // tf32 proj_w transposed [n][k]
__device__ float g_wff1[DFF * DD];       // tf32 ff1_w transposed [n][k]
__device__ float g_wff2[DD * DFF];       // tf32 ff2_w transposed [n][k]

// ==================== helpers ==============================================
__device__ __forceinline__ uint32_t f2tf32(float x) {
    uint32_t t;
    asm("cvt.rna.tf32.f32 %0, %1;" : "=r"(t) : "f"(x));
    return t;
}
__device__ __forceinline__ float rtf(float x) {
    return __uint_as_float(f2tf32(x));
}
__device__ __forceinline__ void mma_tf32(float* c, const uint32_t* a,
                                         const uint32_t* b) {
    asm volatile(
        "mma.sync.aligned.m16n8k8.row.col.f32.tf32.tf32.f32 "
        "{%0,%1,%2,%3}, {%4,%5,%6,%7}, {%8,%9}, {%0,%1,%2,%3};\n"
        : "+f"(c[0]), "+f"(c[1]), "+f"(c[2]), "+f"(c[3])
        : "r"(a[0]), "r"(a[1]), "r"(a[2]), "r"(a[3]),
          "r"(b[0]), "r"(b[1]));
}
__device__ __forceinline__ uint32_t s2u(const void* p) {
    return (uint32_t)__cvta_generic_to_shared(p);
}
__device__ __forceinline__ void cpasync16(uint32_t dst, const void* src) {
    asm volatile("cp.async.ca.shared.global [%0], [%1], 16;\n"
                 :: "r"(dst), "l"(src));
}
#define LDMX4(r0, r1, r2, r3, addr) \
    asm volatile("ldmatrix.sync.aligned.m8n8.x4.shared.b16 {%0,%1,%2,%3}, [%4];" \
                 : "=r"(r0), "=r"(r1), "=r"(r2), "=r"(r3) : "r"(addr))

// ==================== tiled transpose + tf32 round: dst[n][k] = src[k][n] ===
__global__ void transpose_round_kernel(const float* __restrict__ src,
                                       float* __restrict__ dst,
                                       int K, int N)
{
    __shared__ float t[32][33];
    int n0 = blockIdx.x * 32, k0 = blockIdx.y * 32;
    int tx = threadIdx.x;
#pragma unroll
    for (int i = threadIdx.y; i < 32; i += 8)
        t[i][tx] = src[(size_t)(k0 + i) * N + n0 + tx];
    __syncthreads();
#pragma unroll
    for (int i = threadIdx.y; i < 32; i += 8)
        dst[(size_t)(n0 + i) * K + k0 + tx] = rtf(t[tx][i]);
}

// ==================== qkv repack (transposed): W_T[n][d], tf32 ==============
__global__ void repack_kernel(const float* __restrict__ wq,
                              const float* __restrict__ wk,
                              const float* __restrict__ wv,
                              float* __restrict__ WT)
{
    int idx = blockIdx.x * 256 + threadIdx.x;   // idx = n*DD + d
    if (idx >= DD * QKV_N) return;
    int d = idx & (DD - 1);
    int n = idx >> 10;
    int sel = n >> 10;
    int nn  = n & 1023;
    int hh  = nn >> 6;
    int e   = nn & 63;
    const float* src = (sel == 0) ? wq : (sel == 1) ? wk : wv;
    WT[idx] = rtf(src[((size_t)hh * DD + d) * HSZ + e]);
}

// ==================== LayerNorm (tf32-rounded output) =======================
__global__ void ln_kernel(const float* __restrict__ in,
                          const float* __restrict__ gg,
                          const float* __restrict__ bb,
                          float* __restrict__ out)
{
    int row = blockIdx.x;
    const float* x = in + (size_t)row * DD;
    float v[4];
    float s = 0.f, s2 = 0.f;
#pragma unroll
    for (int k = 0; k < 4; k++) {
        v[k] = x[threadIdx.x + k * 256];
        s  += v[k];
        s2 += v[k] * v[k];
    }
#pragma unroll
    for (int off = 16; off; off >>= 1) {
        s  += __shfl_xor_sync(0xffffffffu, s,  off);
        s2 += __shfl_xor_sync(0xffffffffu, s2, off);
    }
    __shared__ float red[2][8];
    int wid = threadIdx.x >> 5, lane = threadIdx.x & 31;
    if (lane == 0) { red[0][wid] = s; red[1][wid] = s2; }
    __syncthreads();
    float S = 0.f, S2 = 0.f;
#pragma unroll
    for (int w = 0; w < 8; w++) { S += red[0][w]; S2 += red[1][w]; }
    float mean = S * (1.0f / DD);
    float var  = S2 * (1.0f / DD) - mean * mean;
    float rstd = rsqrtf(var + 1e-5f);
    float* o = out + (size_t)row * DD;
#pragma unroll
    for (int k = 0; k < 4; k++) {
        int c = threadIdx.x + k * 256;
        o[c] = rtf((v[k] - mean) * rstd * gg[c] + bb[c]);
    }
}

// ==================== TF32 GEMM: ldmatrix + 3-stage cp.async ================
// C[M,N] = A[M,K] @ B_T[N,K]^T.  A row-major [M][K]; BT N-major [N][K].
// Both pre-rounded to tf32.  flags: 1=+bias, 2=+res, 4=relu, 8=round out
#define STAGE_WORDS (128 * 36)
#define STAGE_BYTES (STAGE_WORDS * 4)
#define GEMM_SMEM_BYTES (6 * STAGE_BYTES)    // 3 stages x (A + B)

__global__ __launch_bounds__(256, 2)
void tf32gemm_kernel(int M, int N, int K,
                     const float* __restrict__ A,
                     const float* __restrict__ BT,
                     const float* __restrict__ bias,
                     const float* __restrict__ res,
                     float* __restrict__ C,
                     int flags)
{
    extern __shared__ __align__(16) uint32_t dsm[];
    // stages: A in dsm[buf*STAGE_WORDS], B in dsm[(3+buf)*STAGE_WORDS]

    int tid  = threadIdx.x;
    int lane = tid & 31;
    int warp = tid >> 5;
    int g    = lane >> 2;
    int tig  = lane & 3;
    int warp_m = warp & 1;
    int warp_n = warp >> 1;
    int m0 = blockIdx.y * 128;
    int n0 = blockIdx.x * 128;

    float acc[4][4][4];
#pragma unroll
    for (int i = 0; i < 4; i++)
#pragma unroll
        for (int j = 0; j < 4; j++)
#pragma unroll
            for (int c = 0; c < 4; c++) acc[i][j][c] = 0.f;

    // ldmatrix per-lane base addresses (bytes)
    uint32_t smbase = s2u(dsm);
    uint32_t aAddr = smbase +
        (((warp_m * 64 + (lane & 15)) * 36 + ((lane >> 4) << 2)) << 2);
    uint32_t bAddr = smbase + 3 * STAGE_BYTES +
        (((warp_n * 32 + ((lane >> 3) & 1) * 8 + (lane & 7)) * 36 +
          ((lane >> 4) << 2)) << 2);

    // cp.async assignments: 4 chunks each for A and B per stage
    int r  = tid >> 1;                 // unused helper
    (void)r;

    auto load_tiles = [&](int k0, int buf) {
        uint32_t* as = dsm + buf * STAGE_WORDS;
        uint32_t* bs = dsm + (3 + buf) * STAGE_WORDS;
#pragma unroll
        for (int q = 0; q < 4; q++) {           // A tile 128x32: 1024 chunks
            int ch = q * 256 + tid;
            int rr = ch >> 3, cc = ch & 7;
            cpasync16(s2u(as + rr * 36 + cc * 4),
                      A + (size_t)(m0 + rr) * K + k0 + cc * 4);
        }
#pragma unroll
        for (int q = 0; q < 4; q++) {           // B tile 128x32: 1024 chunks
            int ch = q * 256 + tid;
            int rr = ch >> 3, cc = ch & 7;
            cpasync16(s2u(bs + rr * 36 + cc * 4),
                      BT + (size_t)(n0 + rr) * K + k0 + cc * 4);
        }
    };

    int nk = K / 32;
    load_tiles(0, 0);
    asm volatile("cp.async.commit_group;\n");
    load_tiles(32, 1);
    asm volatile("cp.async.commit_group;\n");

    for (int kt = 0; kt < nk; kt++) {
        if (kt + 1 < nk)
            asm volatile("cp.async.wait_group 1;\n");
        else
            asm volatile("cp.async.wait_group 0;\n");
        __syncthreads();

        if (kt + 2 < nk) {
            load_tiles((kt + 2) * 32, (kt + 2) % 3);
            asm volatile("cp.async.commit_group;\n");
        }

        int buf = kt % 3;
        uint32_t ab = aAddr + buf * STAGE_BYTES;
        uint32_t bb = bAddr + buf * STAGE_BYTES;
#pragma unroll
        for (int ks = 0; ks < 4; ks++) {
            uint32_t afr[4][4], bfr[4][2];
#pragma unroll
            for (int i = 0; i < 4; i++)
                LDMX4(afr[i][0], afr[i][1], afr[i][2], afr[i][3],
                      ab + i * (16 * 36 * 4) + ks * 32);
            {
                uint32_t r0, r1, r2, r3;
                LDMX4(r0, r1, r2, r3, bb + ks * 32);
                bfr[0][0] = r0; bfr[0][1] = r2;
                bfr[1][0] = r1; bfr[1][1] = r3;
                LDMX4(r0, r1, r2, r3, bb + (16 * 36 * 4) + ks * 32);
                bfr[2][0] = r0; bfr[2][1] = r2;
                bfr[3][0] = r1; bfr[3][1] = r3;
            }
#pragma unroll
            for (int i = 0; i < 4; i++)
#pragma unroll
                for (int j = 0; j < 4; j++)
                    mma_tf32(acc[i][j], afr[i], bfr[j]);
        }
    }

    // ---- epilogue ----
#pragma unroll
    for (int j = 0; j < 4; j++) {
        int col = n0 + warp_n * 32 + j * 8 + 2 * tig;
        float b0 = 0.f, b1 = 0.f;
        if (flags & 1) { b0 = bias[col]; b1 = bias[col + 1]; }
#pragma unroll
        for (int i = 0; i < 4; i++) {
            int rr = m0 + warp_m * 64 + i * 16 + g;
#pragma unroll
            for (int half = 0; half < 2; half++) {
                int row = rr + half * 8;
                size_t base = (size_t)row * N + col;
                float v0 = acc[i][j][half * 2 + 0] + b0;
                float v1 = acc[i][j][half * 2 + 1] + b1;
                if (flags & 2) {
                    float2 rv = *(const float2*)(res + base);
                    v0 += rv.x; v1 += rv.y;
                }
                if (flags & 4) { v0 = fmaxf(v0, 0.f); v1 = fmaxf(v1, 0.f); }
                if (flags & 8) { v0 = rtf(v0); v1 = rtf(v1); }
                *(float2*)(C + base) = make_float2(v0, v1);
            }
        }
    }
}

// ==================== TF32 tensor-core flash attention ======================
#define ATT_SMEM_BYTES ((128*68 + 128*68 + 64*72) * 4)

__global__ __launch_bounds__(256, 2)
void attn_tc_kernel(const float* __restrict__ qkv, float* __restrict__ O)
{
    extern __shared__ uint32_t sm[];
    uint32_t* Qs = sm;                   // [128][68]
    uint32_t* KP = sm + 128 * 68;        // Ks[64][68] / Ps[128][68]
    uint32_t* Vs = sm + 2 * 128 * 68;    // [64][72]

    int b  = blockIdx.z;
    int h  = blockIdx.y;
    int q0 = blockIdx.x * 128;
    int tid  = threadIdx.x;
    int lane = tid & 31, warp = tid >> 5;
    int g    = lane >> 2, tig = lane & 3;

    {
        int r  = tid >> 1;
        int c0 = (tid & 1) * 32;
        const float* src = qkv + (size_t)(b * SS + q0 + r) * QKV_N + h * HSZ + c0;
#pragma unroll
        for (int q = 0; q < 8; q++)
            *(uint4*)&Qs[r * 68 + c0 + q * 4] = *(const uint4*)(src + q * 4);
    }

    float o_[8][4];
#pragma unroll
    for (int n = 0; n < 8; n++)
#pragma unroll
        for (int c = 0; c < 4; c++) o_[n][c] = 0.f;
    float m0 = -1e30f, m8 = -1e30f, l0 = 0.f, l8 = 0.f;

    int Rw   = q0 + warp * 16;
    int row0 = Rw + g;
    int rmax = Rw + 15;
    int rloc = warp * 16 + g;

    int ntile = 2 * blockIdx.x + 2;
    for (int jt = 0; jt < ntile; jt++) {
        int j0 = jt * 64;
        __syncthreads();
        {
            int t  = tid >> 2;
            int c0 = (tid & 3) * 16;
            const float* kp = qkv + (size_t)(b * SS + j0 + t) * QKV_N + DD + h * HSZ + c0;
#pragma unroll
            for (int q = 0; q < 4; q++) {
                *(uint4*)&KP[t * 68 + c0 + q * 4] = *(const uint4*)(kp + q * 4);
                *(uint4*)&Vs[t * 72 + c0 + q * 4] = *(const uint4*)(kp + DD + q * 4);
            }
        }
        __syncthreads();

        bool active = (j0 <= rmax);
        float p[8][4];
        if (active) {
#pragma unroll
            for (int n = 0; n < 8; n++)
#pragma unroll
                for (int c = 0; c < 4; c++) p[n][c] = 0.f;
#pragma unroll
            for (int ks = 0; ks < 8; ks++) {
                int kb = ks * 8;
                uint32_t a[4];
                a[0] = Qs[rloc * 68 + kb + tig];
                a[1] = Qs[(rloc + 8) * 68 + kb + tig];
                a[2] = Qs[rloc * 68 + kb + tig + 4];
                a[3] = Qs[(rloc + 8) * 68 + kb + tig + 4];
#pragma unroll
                for (int n = 0; n < 8; n++) {
                    uint32_t bf[2];
                    bf[0] = KP[(n * 8 + g) * 68 + kb + tig];
                    bf[1] = KP[(n * 8 + g) * 68 + kb + tig + 4];
                    mma_tf32(p[n], a, bf);
                }
            }
            bool needmask = (j0 + 63 > Rw);
            float mt0 = -1e30f, mt8 = -1e30f;
#pragma unroll
            for (int n = 0; n < 8; n++) {
#pragma unroll
                for (int c = 0; c < 4; c++) {
                    float v = p[n][c] * 0.125f;
                    if (needmask) {
                        int col = j0 + n * 8 + 2 * tig + (c & 1);
                        int row = row0 + (c >> 1) * 8;
                        if (col > row) v = -1e30f;
                    }
                    p[n][c] = v;
                    if (c < 2) mt0 = fmaxf(mt0, v); else mt8 = fmaxf(mt8, v);
                }
            }
            mt0 = fmaxf(mt0, __shfl_xor_sync(0xffffffffu, mt0, 1));
            mt0 = fmaxf(mt0, __shfl_xor_sync(0xffffffffu, mt0, 2));
            mt8 = fmaxf(mt8, __shfl_xor_sync(0xffffffffu, mt8, 1));
            mt8 = fmaxf(mt8, __shfl_xor_sync(0xffffffffu, mt8, 2));
            float nm0 = fmaxf(m0, mt0), nm8 = fmaxf(m8, mt8);
            float al0 = __expf(m0 - nm0), al8 = __expf(m8 - nm8);
            m0 = nm0; m8 = nm8;
            float ps0 = 0.f, ps8 = 0.f;
#pragma unroll
            for (int n = 0; n < 8; n++) {
                p[n][0] = __expf(p[n][0] - nm0);
                p[n][1] = __expf(p[n][1] - nm0);
                p[n][2] = __expf(p[n][2] - nm8);
                p[n][3] = __expf(p[n][3] - nm8);
                ps0 += p[n][0] + p[n][1];
                ps8 += p[n][2] + p[n][3];
            }
            ps0 += __shfl_xor_sync(0xffffffffu, ps0, 1);
            ps0 += __shfl_xor_sync(0xffffffffu, ps0, 2);
            ps8 += __shfl_xor_sync(0xffffffffu, ps8, 1);
            ps8 += __shfl_xor_sync(0xffffffffu, ps8, 2);
            l0 = l0 * al0 + ps0;
            l8 = l8 * al8 + ps8;
#pragma unroll
            for (int n = 0; n < 8; n++) {
                o_[n][0] *= al0; o_[n][1] *= al0;
                o_[n][2] *= al8; o_[n][3] *= al8;
            }
        }
        __syncthreads();

        if (active) {
#pragma unroll
            for (int n = 0; n < 8; n++) {
                uint2 lo = make_uint2(f2tf32(p[n][0]), f2tf32(p[n][1]));
                uint2 hi = make_uint2(f2tf32(p[n][2]), f2tf32(p[n][3]));
                *(uint2*)&KP[rloc * 68 + n * 8 + 2 * tig] = lo;
                *(uint2*)&KP[(rloc + 8) * 68 + n * 8 + 2 * tig] = hi;
            }
#pragma unroll
            for (int ks = 0; ks < 8; ks++) {
                int kb = ks * 8;
                uint32_t a[4];
                a[0] = KP[rloc * 68 + kb + tig];
                a[1] = KP[(rloc + 8) * 68 + kb + tig];
                a[2] = KP[rloc * 68 + kb + tig + 4];
                a[3] = KP[(rloc + 8) * 68 + kb + tig + 4];
#pragma unroll
                for (int n = 0; n < 8; n++) {
                    uint32_t bf[2];
                    bf[0] = Vs[(kb + tig) * 72 + n * 8 + g];
                    bf[1] = Vs[(kb + tig + 4) * 72 + n * 8 + g];
                    mma_tf32(o_[n], a, bf);
                }
            }
        }
    }

    float inv0 = 1.0f / l0, inv8 = 1.0f / l8;
    size_t base0 = (size_t)(b * SS + q0 + rloc) * DD + h * HSZ;
    size_t base8 = base0 + 8 * DD;
#pragma unroll
    for (int n = 0; n < 8; n++) {
        int col = n * 8 + 2 * tig;
        *(float2*)&O[base0 + col] =
            make_float2(rtf(o_[n][0] * inv0), rtf(o_[n][1] * inv0));
        *(float2*)&O[base8 + col] =
            make_float2(rtf(o_[n][2] * inv8), rtf(o_[n][3] * inv8));
    }
}

// ==================== host launcher ========================================
extern "C" void kernel_launch(void* const* d_in, const int* in_sizes, int n_in,
                              void* d_out, int out_size)
{
    const float* x      = (const float*)d_in[0];
    const float* wq     = (const float*)d_in[1];
    const float* wk     = (const float*)d_in[2];
    const float* wv     = (const float*)d_in[3];
    const float* proj_w = (const float*)d_in[4];
    const float* proj_b = (const float*)d_in[5];
    const float* ff1_w  = (const float*)d_in[6];
    const float* ff1_b  = (const float*)d_in[7];
    const float* ff2_w  = (const float*)d_in[8];
    const float* ff2_b  = (const float*)d_in[9];
    const float* ln1_g  = (const float*)d_in[10];
    const float* ln1_b  = (const float*)d_in[11];
    const float* ln2_g  = (const float*)d_in[12];
    const float* ln2_b  = (const float*)d_in[13];
    float* out = (float*)d_out;

    static float *h = nullptr, *qkv, *wpack, *o, *ffh, *wproj, *wff1, *wff2;
    if (!h) {
        cudaGetSymbolAddress((void**)&h,     g_h);
        cudaGetSymbolAddress((void**)&qkv,   g_qkv);
        cudaGetSymbolAddress((void**)&wpack, g_wqkv);
        cudaGetSymbolAddress((void**)&o,     g_o);
        cudaGetSymbolAddress((void**)&ffh,   g_ffh);
        cudaGetSymbolAddress((void**)&wproj, g_wproj);
        cudaGetSymbolAddress((void**)&wff1,  g_wff1);
        cudaGetSymbolAddress((void**)&wff2,  g_wff2);
        cudaFuncSetAttribute(attn_tc_kernel,
                             cudaFuncAttributeMaxDynamicSharedMemorySize,
                             ATT_SMEM_BYTES);
        cudaFuncSetAttribute(tf32gemm_kernel,
                             cudaFuncAttributeMaxDynamicSharedMemorySize,
                             GEMM_SMEM_BYTES);
    }

    // 0. weight prep: transposed + tf32-rounded copies
    repack_kernel<<<(DD * QKV_N + 255) / 256, 256>>>(wq, wk, wv, wpack);
    transpose_round_kernel<<<dim3(DD / 32, DD / 32),  dim3(32, 8)>>>(proj_w, wproj, DD,  DD);
    transpose_round_kernel<<<dim3(DFF / 32, DD / 32), dim3(32, 8)>>>(ff1_w,  wff1,  DD,  DFF);
    transpose_round_kernel<<<dim3(DD / 32, DFF / 32), dim3(32, 8)>>>(ff2_w,  wff2,  DFF, DD);
    // 1. h = LN1(x)
    ln_kernel<<<NROWS, 256>>>(x, ln1_g, ln1_b, h);
    // 2. qkv = h @ Wqkv  (round output)
    tf32gemm_kernel<<<dim3(QKV_N / 128, NROWS / 128), 256, GEMM_SMEM_BYTES>>>(
        NROWS, QKV_N, DD, h, wpack, nullptr, nullptr, qkv, 8);
    // 3. flash attention
    attn_tc_kernel<<<dim3(SS / 128, HH, BB), 256, ATT_SMEM_BYTES>>>(qkv, o);
    // 4. out = x + o @ proj_w + proj_b
    tf32gemm_kernel<<<dim3(DD / 128, NROWS / 128), 256, GEMM_SMEM_BYTES>>>(
        NROWS, DD, DD, o, wproj, proj_b, x, out, 1 | 2);
    // 5. h = LN2(out)
    ln_kernel<<<NROWS, 256>>>(out, ln2_g, ln2_b, h);
    // 6. ffh = relu(h @ ff1_w + ff1_b)  (round output)
    tf32gemm_kernel<<<dim3(DFF / 128, NROWS / 128), 256, GEMM_SMEM_BYTES>>>(
        NROWS, DFF, DD, h, wff1, ff1_b, nullptr, ffh, 1 | 4 | 8);
    // 7. out += ffh @ ff2_w + ff2_b
    tf32gemm_kernel<<<dim3(DD / 128, NROWS / 128), 256, GEMM_SMEM_BYTES>>>(
        NROWS, DD, DFF, ffh, wff2, ff2_b, out, out, 1 | 2);
}

// round 9
// speedup vs baseline: 1.1571x; 1.1571x over previous
#include <cuda_runtime.h>
#include <cuda_bf16.h>
#include <math.h>
#include <stdint.h>

// ---------------- problem constants ----------------
#define BB 4
#define SS 2048
#define DD 1024
#define HH 16
#define HSZ 64
#define DFF 4096
#define NROWS (BB * SS)          // 8192
#define QKV_N (3 * DD)           // 3072

// ---------------- scratch (static device globals; no cudaMalloc allowed) ----
__device__ float g_h[NROWS * DD];        // LN output (tf32-rounded)
__device__ float g_qkv[NROWS * QKV_N];   // Q|K|V, head-concat (tf32-rounded)
__device__ float g_wqkv[QKV_N * DD];     // packed qkv weights TRANSPOSED [n][d]
__device__ float g_o[NROWS * DD];        // attention output (tf32-rounded)
__device__ float g_ffh[NROWS * DFF];     // FFN hidden (tf32-rounded)
__device__ float g_wproj[DD * DD];       // tf32 proj_w transposed [n][k]
__device__ float g_wff1[DFF * DD];       // tf32 ff1_w transposed [n][k]
__device__ float g_wff2[DD * DFF];       // tf32 ff2_w transposed [n][k]

// ==================== helpers ==============================================
__device__ __forceinline__ uint32_t f2tf32(float x) {
    uint32_t t;
    asm("cvt.rna.tf32.f32 %0, %1;" : "=r"(t) : "f"(x));
    return t;
}
__device__ __forceinline__ float rtf(float x) {
    return __uint_as_float(f2tf32(x));
}
__device__ __forceinline__ void mma_tf32(float* c, const uint32_t* a,
                                         const uint32_t* b) {
    asm volatile(
        "mma.sync.aligned.m16n8k8.row.col.f32.tf32.tf32.f32 "
        "{%0,%1,%2,%3}, {%4,%5,%6,%7}, {%8,%9}, {%0,%1,%2,%3};\n"
        : "+f"(c[0]), "+f"(c[1]), "+f"(c[2]), "+f"(c[3])
        : "r"(a[0]), "r"(a[1]), "r"(a[2]), "r"(a[3]),
          "r"(b[0]), "r"(b[1]));
}
__device__ __forceinline__ uint32_t s2u(const void* p) {
    return (uint32_t)__cvta_generic_to_shared(p);
}
__device__ __forceinline__ void cpasync16(uint32_t dst, const void* src) {
    asm volatile("cp.async.ca.shared.global [%0], [%1], 16;\n"
                 :: "r"(dst), "l"(src));
}
#define LDMX4(r0, r1, r2, r3, addr) \
    asm volatile("ldmatrix.sync.aligned.m8n8.x4.shared.b16 {%0,%1,%2,%3}, [%4];" \
                 : "=r"(r0), "=r"(r1), "=r"(r2), "=r"(r3) : "r"(addr))

// ==================== tiled transpose + tf32 round: dst[n][k] = src[k][n] ===
__global__ void transpose_round_kernel(const float* __restrict__ src,
                                       float* __restrict__ dst,
                                       int K, int N)
{
    __shared__ float t[32][33];
    int n0 = blockIdx.x * 32, k0 = blockIdx.y * 32;
    int tx = threadIdx.x;
#pragma unroll
    for (int i = threadIdx.y; i < 32; i += 8)
        t[i][tx] = src[(size_t)(k0 + i) * N + n0 + tx];
    __syncthreads();
#pragma unroll
    for (int i = threadIdx.y; i < 32; i += 8)
        dst[(size_t)(n0 + i) * K + k0 + tx] = rtf(t[tx][i]);
}

// ==================== qkv repack (transposed): W_T[n][d], tf32 ==============
__global__ void repack_kernel(const float* __restrict__ wq,
                              const float* __restrict__ wk,
                              const float* __restrict__ wv,
                              float* __restrict__ WT)
{
    int idx = blockIdx.x * 256 + threadIdx.x;   // idx = n*DD + d
    if (idx >= DD * QKV_N) return;
    int d = idx & (DD - 1);
    int n = idx >> 10;
    int sel = n >> 10;
    int nn  = n & 1023;
    int hh  = nn >> 6;
    int e   = nn & 63;
    const float* src = (sel == 0) ? wq : (sel == 1) ? wk : wv;
    WT[idx] = rtf(src[((size_t)hh * DD + d) * HSZ + e]);
}

// ==================== LayerNorm (tf32-rounded output) =======================
__global__ void ln_kernel(const float* __restrict__ in,
                          const float* __restrict__ gg,
                          const float* __restrict__ bb,
                          float* __restrict__ out)
{
    int row = blockIdx.x;
    const float* x = in + (size_t)row * DD;
    float v[4];
    float s = 0.f, s2 = 0.f;
#pragma unroll
    for (int k = 0; k < 4; k++) {
        v[k] = x[threadIdx.x + k * 256];
        s  += v[k];
        s2 += v[k] * v[k];
    }
#pragma unroll
    for (int off = 16; off; off >>= 1) {
        s  += __shfl_xor_sync(0xffffffffu, s,  off);
        s2 += __shfl_xor_sync(0xffffffffu, s2, off);
    }
    __shared__ float red[2][8];
    int wid = threadIdx.x >> 5, lane = threadIdx.x & 31;
    if (lane == 0) { red[0][wid] = s; red[1][wid] = s2; }
    __syncthreads();
    float S = 0.f, S2 = 0.f;
#pragma unroll
    for (int w = 0; w < 8; w++) { S += red[0][w]; S2 += red[1][w]; }
    float mean = S * (1.0f / DD);
    float var  = S2 * (1.0f / DD) - mean * mean;
    float rstd = rsqrtf(var + 1e-5f);
    float* o = out + (size_t)row * DD;
#pragma unroll
    for (int k = 0; k < 4; k++) {
        int c = threadIdx.x + k * 256;
        o[c] = rtf((v[k] - mean) * rstd * gg[c] + bb[c]);
    }
}

// ==================== TF32 GEMM: ldmatrix + 2-stage cp.async ================
// C[M,N] = A[M,K] @ B_T[N,K]^T.  A row-major [M][K]; BT N-major [N][K].
// Both pre-rounded to tf32.  flags: 1=+bias, 2=+res, 4=relu, 8=round out
#define STAGE_WORDS (128 * 36)
#define STAGE_BYTES (STAGE_WORDS * 4)
#define GEMM_SMEM_BYTES (4 * STAGE_BYTES)    // 2 stages x (A + B) = 73.7 KB

__global__ __launch_bounds__(256, 2)
void tf32gemm_kernel(int M, int N, int K,
                     const float* __restrict__ A,
                     const float* __restrict__ BT,
                     const float* __restrict__ bias,
                     const float* __restrict__ res,
                     float* __restrict__ C,
                     int flags)
{
    extern __shared__ __align__(16) uint32_t dsm[];
    // A stages at dsm[buf*STAGE_WORDS], B stages at dsm[(2+buf)*STAGE_WORDS]

    int tid  = threadIdx.x;
    int lane = tid & 31;
    int warp = tid >> 5;
    int g    = lane >> 2;
    int tig  = lane & 3;
    int warp_m = warp & 1;
    int warp_n = warp >> 1;
    int m0 = blockIdx.y * 128;
    int n0 = blockIdx.x * 128;

    float acc[4][4][4];
#pragma unroll
    for (int i = 0; i < 4; i++)
#pragma unroll
        for (int j = 0; j < 4; j++)
#pragma unroll
            for (int c = 0; c < 4; c++) acc[i][j][c] = 0.f;

    // ldmatrix per-lane base addresses (bytes)
    uint32_t smbase = s2u(dsm);
    uint32_t aAddr = smbase +
        (((warp_m * 64 + (lane & 15)) * 36 + ((lane >> 4) << 2)) << 2);
    uint32_t bAddr = smbase + 2 * STAGE_BYTES +
        (((warp_n * 32 + ((lane >> 3) & 1) * 8 + (lane & 7)) * 36 +
          ((lane >> 4) << 2)) << 2);

    auto load_tiles = [&](int k0, int buf) {
        uint32_t* as = dsm + buf * STAGE_WORDS;
        uint32_t* bs = dsm + (2 + buf) * STAGE_WORDS;
#pragma unroll
        for (int q = 0; q < 4; q++) {           // A tile 128x32: 1024 chunks
            int ch = q * 256 + tid;
            int rr = ch >> 3, cc = ch & 7;
            cpasync16(s2u(as + rr * 36 + cc * 4),
                      A + (size_t)(m0 + rr) * K + k0 + cc * 4);
        }
#pragma unroll
        for (int q = 0; q < 4; q++) {           // B tile 128x32: 1024 chunks
            int ch = q * 256 + tid;
            int rr = ch >> 3, cc = ch & 7;
            cpasync16(s2u(bs + rr * 36 + cc * 4),
                      BT + (size_t)(n0 + rr) * K + k0 + cc * 4);
        }
    };

    load_tiles(0, 0);
    asm volatile("cp.async.commit_group;\n");

    int nk = K / 32;
    for (int kt = 0; kt < nk; kt++) {
        int cur = kt & 1;
        if (kt + 1 < nk) {
            load_tiles((kt + 1) * 32, cur ^ 1);
            asm volatile("cp.async.commit_group;\n");
            asm volatile("cp.async.wait_group 1;\n");
        } else {
            asm volatile("cp.async.wait_group 0;\n");
        }
        __syncthreads();

        uint32_t ab = aAddr + cur * STAGE_BYTES;
        uint32_t bb = bAddr + cur * STAGE_BYTES;
#pragma unroll
        for (int ks = 0; ks < 4; ks++) {
            uint32_t afr[4][4], bfr[4][2];
#pragma unroll
            for (int i = 0; i < 4; i++)
                LDMX4(afr[i][0], afr[i][1], afr[i][2], afr[i][3],
                      ab + i * (16 * 36 * 4) + ks * 32);
            {
                uint32_t r0, r1, r2, r3;
                LDMX4(r0, r1, r2, r3, bb + ks * 32);
                bfr[0][0] = r0; bfr[0][1] = r2;
                bfr[1][0] = r1; bfr[1][1] = r3;
                LDMX4(r0, r1, r2, r3, bb + (16 * 36 * 4) + ks * 32);
                bfr[2][0] = r0; bfr[2][1] = r2;
                bfr[3][0] = r1; bfr[3][1] = r3;
            }
#pragma unroll
            for (int i = 0; i < 4; i++)
#pragma unroll
                for (int j = 0; j < 4; j++)
                    mma_tf32(acc[i][j], afr[i], bfr[j]);
        }
        __syncthreads();   // buffer cur is being refilled next iteration
    }

    // ---- epilogue ----
#pragma unroll
    for (int j = 0; j < 4; j++) {
        int col = n0 + warp_n * 32 + j * 8 + 2 * tig;
        float b0 = 0.f, b1 = 0.f;
        if (flags & 1) { b0 = bias[col]; b1 = bias[col + 1]; }
#pragma unroll
        for (int i = 0; i < 4; i++) {
            int rr = m0 + warp_m * 64 + i * 16 + g;
#pragma unroll
            for (int half = 0; half < 2; half++) {
                int row = rr + half * 8;
                size_t base = (size_t)row * N + col;
                float v0 = acc[i][j][half * 2 + 0] + b0;
                float v1 = acc[i][j][half * 2 + 1] + b1;
                if (flags & 2) {
                    float2 rv = *(const float2*)(res + base);
                    v0 += rv.x; v1 += rv.y;
                }
                if (flags & 4) { v0 = fmaxf(v0, 0.f); v1 = fmaxf(v1, 0.f); }
                if (flags & 8) { v0 = rtf(v0); v1 = rtf(v1); }
                *(float2*)(C + base) = make_float2(v0, v1);
            }
        }
    }
}

// ==================== TF32 tensor-core flash attention ======================
#define ATT_SMEM_BYTES ((128*68 + 128*68 + 64*72) * 4)

__global__ __launch_bounds__(256, 2)
void attn_tc_kernel(const float* __restrict__ qkv, float* __restrict__ O)
{
    extern __shared__ uint32_t sm[];
    uint32_t* Qs = sm;                   // [128][68]
    uint32_t* KP = sm + 128 * 68;        // Ks[64][68] / Ps[128][68]
    uint32_t* Vs = sm + 2 * 128 * 68;    // [64][72]

    int b  = blockIdx.z;
    int h  = blockIdx.y;
    int q0 = blockIdx.x * 128;
    int tid  = threadIdx.x;
    int lane = tid & 31, warp = tid >> 5;
    int g    = lane >> 2, tig = lane & 3;

    {
        int r  = tid >> 1;
        int c0 = (tid & 1) * 32;
        const float* src = qkv + (size_t)(b * SS + q0 + r) * QKV_N + h * HSZ + c0;
#pragma unroll
        for (int q = 0; q < 8; q++)
            *(uint4*)&Qs[r * 68 + c0 + q * 4] = *(const uint4*)(src + q * 4);
    }

    float o_[8][4];
#pragma unroll
    for (int n = 0; n < 8; n++)
#pragma unroll
        for (int c = 0; c < 4; c++) o_[n][c] = 0.f;
    float m0 = -1e30f, m8 = -1e30f, l0 = 0.f, l8 = 0.f;

    int Rw   = q0 + warp * 16;
    int row0 = Rw + g;
    int rmax = Rw + 15;
    int rloc = warp * 16 + g;

    int ntile = 2 * blockIdx.x + 2;
    for (int jt = 0; jt < ntile; jt++) {
        int j0 = jt * 64;
        __syncthreads();
        {
            int t  = tid >> 2;
            int c0 = (tid & 3) * 16;
            const float* kp = qkv + (size_t)(b * SS + j0 + t) * QKV_N + DD + h * HSZ + c0;
#pragma unroll
            for (int q = 0; q < 4; q++) {
                *(uint4*)&KP[t * 68 + c0 + q * 4] = *(const uint4*)(kp + q * 4);
                *(uint4*)&Vs[t * 72 + c0 + q * 4] = *(const uint4*)(kp + DD + q * 4);
            }
        }
        __syncthreads();

        bool active = (j0 <= rmax);
        float p[8][4];
        if (active) {
#pragma unroll
            for (int n = 0; n < 8; n++)
#pragma unroll
                for (int c = 0; c < 4; c++) p[n][c] = 0.f;
#pragma unroll
            for (int ks = 0; ks < 8; ks++) {
                int kb = ks * 8;
                uint32_t a[4];
                a[0] = Qs[rloc * 68 + kb + tig];
                a[1] = Qs[(rloc + 8) * 68 + kb + tig];
                a[2] = Qs[rloc * 68 + kb + tig + 4];
                a[3] = Qs[(rloc + 8) * 68 + kb + tig + 4];
#pragma unroll
                for (int n = 0; n < 8; n++) {
                    uint32_t bf[2];
                    bf[0] = KP[(n * 8 + g) * 68 + kb + tig];
                    bf[1] = KP[(n * 8 + g) * 68 + kb + tig + 4];
                    mma_tf32(p[n], a, bf);
                }
            }
            bool needmask = (j0 + 63 > Rw);
            float mt0 = -1e30f, mt8 = -1e30f;
#pragma unroll
            for (int n = 0; n < 8; n++) {
#pragma unroll
                for (int c = 0; c < 4; c++) {
                    float v = p[n][c] * 0.125f;
                    if (needmask) {
                        int col = j0 + n * 8 + 2 * tig + (c & 1);
                        int row = row0 + (c >> 1) * 8;
                        if (col > row) v = -1e30f;
                    }
                    p[n][c] = v;
                    if (c < 2) mt0 = fmaxf(mt0, v); else mt8 = fmaxf(mt8, v);
                }
            }
            mt0 = fmaxf(mt0, __shfl_xor_sync(0xffffffffu, mt0, 1));
            mt0 = fmaxf(mt0, __shfl_xor_sync(0xffffffffu, mt0, 2));
            mt8 = fmaxf(mt8, __shfl_xor_sync(0xffffffffu, mt8, 1));
            mt8 = fmaxf(mt8, __shfl_xor_sync(0xffffffffu, mt8, 2));
            float nm0 = fmaxf(m0, mt0), nm8 = fmaxf(m8, mt8);
            float al0 = __expf(m0 - nm0), al8 = __expf(m8 - nm8);
            m0 = nm0; m8 = nm8;
            float ps0 = 0.f, ps8 = 0.f;
#pragma unroll
            for (int n = 0; n < 8; n++) {
                p[n][0] = __expf(p[n][0] - nm0);
                p[n][1] = __expf(p[n][1] - nm0);
                p[n][2] = __expf(p[n][2] - nm8);
                p[n][3] = __expf(p[n][3] - nm8);
                ps0 += p[n][0] + p[n][1];
                ps8 += p[n][2] + p[n][3];
            }
            ps0 += __shfl_xor_sync(0xffffffffu, ps0, 1);
            ps0 += __shfl_xor_sync(0xffffffffu, ps0, 2);
            ps8 += __shfl_xor_sync(0xffffffffu, ps8, 1);
            ps8 += __shfl_xor_sync(0xffffffffu, ps8, 2);
            l0 = l0 * al0 + ps0;
            l8 = l8 * al8 + ps8;
#pragma unroll
            for (int n = 0; n < 8; n++) {
                o_[n][0] *= al0; o_[n][1] *= al0;
                o_[n][2] *= al8; o_[n][3] *= al8;
            }
        }
        __syncthreads();

        if (active) {
#pragma unroll
            for (int n = 0; n < 8; n++) {
                uint2 lo = make_uint2(f2tf32(p[n][0]), f2tf32(p[n][1]));
                uint2 hi = make_uint2(f2tf32(p[n][2]), f2tf32(p[n][3]));
                *(uint2*)&KP[rloc * 68 + n * 8 + 2 * tig] = lo;
                *(uint2*)&KP[(rloc + 8) * 68 + n * 8 + 2 * tig] = hi;
            }
#pragma unroll
            for (int ks = 0; ks < 8; ks++) {
                int kb = ks * 8;
                uint32_t a[4];
                a[0] = KP[rloc * 68 + kb + tig];
                a[1] = KP[(rloc + 8) * 68 + kb + tig];
                a[2] = KP[rloc * 68 + kb + tig + 4];
                a[3] = KP[(rloc + 8) * 68 + kb + tig + 4];
#pragma unroll
                for (int n = 0; n < 8; n++) {
                    uint32_t bf[2];
                    bf[0] = Vs[(kb + tig) * 72 + n * 8 + g];
                    bf[1] = Vs[(kb + tig + 4) * 72 + n * 8 + g];
                    mma_tf32(o_[n], a, bf);
                }
            }
        }
    }

    float inv0 = 1.0f / l0, inv8 = 1.0f / l8;
    size_t base0 = (size_t)(b * SS + q0 + rloc) * DD + h * HSZ;
    size_t base8 = base0 + 8 * DD;
#pragma unroll
    for (int n = 0; n < 8; n++) {
        int col = n * 8 + 2 * tig;
        *(float2*)&O[base0 + col] =
            make_float2(rtf(o_[n][0] * inv0), rtf(o_[n][1] * inv0));
        *(float2*)&O[base8 + col] =
            make_float2(rtf(o_[n][2] * inv8), rtf(o_[n][3] * inv8));
    }
}

// ==================== host launcher ========================================
extern "C" void kernel_launch(void* const* d_in, const int* in_sizes, int n_in,
                              void* d_out, int out_size)
{
    const float* x      = (const float*)d_in[0];
    const float* wq     = (const float*)d_in[1];
    const float* wk     = (const float*)d_in[2];
    const float* wv     = (const float*)d_in[3];
    const float* proj_w = (const float*)d_in[4];
    const float* proj_b = (const float*)d_in[5];
    const float* ff1_w  = (const float*)d_in[6];
    const float* ff1_b  = (const float*)d_in[7];
    const float* ff2_w  = (const float*)d_in[8];
    const float* ff2_b  = (const float*)d_in[9];
    const float* ln1_g  = (const float*)d_in[10];
    const float* ln1_b  = (const float*)d_in[11];
    const float* ln2_g  = (const float*)d_in[12];
    const float* ln2_b  = (const float*)d_in[13];
    float* out = (float*)d_out;

    static float *h = nullptr, *qkv, *wpack, *o, *ffh, *wproj, *wff1, *wff2;
    if (!h) {
        cudaGetSymbolAddress((void**)&h,     g_h);
        cudaGetSymbolAddress((void**)&qkv,   g_qkv);
        cudaGetSymbolAddress((void**)&wpack, g_wqkv);
        cudaGetSymbolAddress((void**)&o,     g_o);
        cudaGetSymbolAddress((void**)&ffh,   g_ffh);
        cudaGetSymbolAddress((void**)&wproj, g_wproj);
        cudaGetSymbolAddress((void**)&wff1,  g_wff1);
        cudaGetSymbolAddress((void**)&wff2,  g_wff2);
        cudaFuncSetAttribute(attn_tc_kernel,
                             cudaFuncAttributeMaxDynamicSharedMemorySize,
                             ATT_SMEM_BYTES);
        cudaFuncSetAttribute(tf32gemm_kernel,
                             cudaFuncAttributeMaxDynamicSharedMemorySize,
                             GEMM_SMEM_BYTES);
    }

    // 0. weight prep: transposed + tf32-rounded copies
    repack_kernel<<<(DD * QKV_N + 255) / 256, 256>>>(wq, wk, wv, wpack);
    transpose_round_kernel<<<dim3(DD / 32, DD / 32),  dim3(32, 8)>>>(proj_w, wproj, DD,  DD);
    transpose_round_kernel<<<dim3(DFF / 32, DD / 32), dim3(32, 8)>>>(ff1_w,  wff1,  DD,  DFF);
    transpose_round_kernel<<<dim3(DD / 32, DFF / 32), dim3(32, 8)>>>(ff2_w,  wff2,  DFF, DD);
    // 1. h = LN1(x)
    ln_kernel<<<NROWS, 256>>>(x, ln1_g, ln1_b, h);
    // 2. qkv = h @ Wqkv  (round output)
    tf32gemm_kernel<<<dim3(QKV_N / 128, NROWS / 128), 256, GEMM_SMEM_BYTES>>>(
        NROWS, QKV_N, DD, h, wpack, nullptr, nullptr, qkv, 8);
    // 3. flash attention
    attn_tc_kernel<<<dim3(SS / 128, HH, BB), 256, ATT_SMEM_BYTES>>>(qkv, o);
    // 4. out = x + o @ proj_w + proj_b
    tf32gemm_kernel<<<dim3(DD / 128, NROWS / 128), 256, GEMM_SMEM_BYTES>>>(
        NROWS, DD, DD, o, wproj, proj_b, x, out, 1 | 2);
    // 5. h = LN2(out)
    ln_kernel<<<NROWS, 256>>>(out, ln2_g, ln2_b, h);
    // 6. ffh = relu(h @ ff1_w + ff1_b)  (round output)
    tf32gemm_kernel<<<dim3(DFF / 128, NROWS / 128), 256, GEMM_SMEM_BYTES>>>(
        NROWS, DFF, DD, h, wff1, ff1_b, nullptr, ffh, 1 | 4 | 8);
    // 7. out += ffh @ ff2_w + ff2_b
    tf32gemm_kernel<<<dim3(DD / 128, NROWS / 128), 256, GEMM_SMEM_BYTES>>>(
        NROWS, DD, DFF, ffh, wff2, ff2_b, out, out, 1 | 2);
}

// round 12
// speedup vs baseline: 1.6063x; 1.3883x over previous
#include <cuda_runtime.h>
#include <cuda_bf16.h>
#include <math.h>
#include <stdint.h>

// ---------------- problem constants ----------------
#define BB 4
#define SS 2048
#define DD 1024
#define HH 16
#define HSZ 64
#define DFF 4096
#define NROWS (BB * SS)          // 8192
#define QKV_N (3 * DD)           // 3072

// ---------------- scratch (bf16 activations/weights) -----------------------
__device__ __nv_bfloat16 g_h[NROWS * DD];        // LN output
__device__ __nv_bfloat16 g_qkv[NROWS * QKV_N];   // Q|K|V head-concat
__device__ __nv_bfloat16 g_wqkv[QKV_N * DD];     // qkv weights T [n][d]
__device__ __nv_bfloat16 g_o[NROWS * DD];        // attention output
__device__ __nv_bfloat16 g_ffh[NROWS * DFF];     // FFN hidden
__device__ __nv_bfloat16 g_wproj[DD * DD];       // proj_w T [n][k]
__device__ __nv_bfloat16 g_wff1[DFF * DD];       // ff1_w T [n][k]
__device__ __nv_bfloat16 g_wff2[DD * DFF];       // ff2_w T [n][k]

// ==================== helpers ==============================================
__device__ __forceinline__ uint32_t f2tf32(float x) {
    uint32_t t;
    asm("cvt.rna.tf32.f32 %0, %1;" : "=r"(t) : "f"(x));
    return t;
}
__device__ __forceinline__ void mma_tf32(float* c, const uint32_t* a,
                                         const uint32_t* b) {
    asm volatile(
        "mma.sync.aligned.m16n8k8.row.col.f32.tf32.tf32.f32 "
        "{%0,%1,%2,%3}, {%4,%5,%6,%7}, {%8,%9}, {%0,%1,%2,%3};\n"
        : "+f"(c[0]), "+f"(c[1]), "+f"(c[2]), "+f"(c[3])
        : "r"(a[0]), "r"(a[1]), "r"(a[2]), "r"(a[3]),
          "r"(b[0]), "r"(b[1]));
}
__device__ __forceinline__ void mma_bf16(float* c, const uint32_t* a,
                                         const uint32_t* b) {
    asm volatile(
        "mma.sync.aligned.m16n8k16.row.col.f32.bf16.bf16.f32 "
        "{%0,%1,%2,%3}, {%4,%5,%6,%7}, {%8,%9}, {%0,%1,%2,%3};\n"
        : "+f"(c[0]), "+f"(c[1]), "+f"(c[2]), "+f"(c[3])
        : "r"(a[0]), "r"(a[1]), "r"(a[2]), "r"(a[3]),
          "r"(b[0]), "r"(b[1]));
}
__device__ __forceinline__ uint32_t s2u(const void* p) {
    return (uint32_t)__cvta_generic_to_shared(p);
}
__device__ __forceinline__ void cpasync16(uint32_t dst, const void* src) {
    asm volatile("cp.async.ca.shared.global [%0], [%1], 16;\n"
                 :: "r"(dst), "l"(src));
}
__device__ __forceinline__ float2 bf2f(uint32_t w) {
    __nv_bfloat162 h = *reinterpret_cast<__nv_bfloat162*>(&w);
    return __bfloat1622float2(h);
}
__device__ __forceinline__ uint32_t f2bfpair(float a, float b) {
    __nv_bfloat162 h = __floats2bfloat162_rn(a, b);
    return *reinterpret_cast<uint32_t*>(&h);
}

// ==================== weight prep ==========================================
__global__ void transpose_round_kernel(const float* __restrict__ src,
                                       __nv_bfloat16* __restrict__ dst,
                                       int K, int N)
{
    __shared__ float t[32][33];
    int n0 = blockIdx.x * 32, k0 = blockIdx.y * 32;
    int tx = threadIdx.x;
#pragma unroll
    for (int i = threadIdx.y; i < 32; i += 8)
        t[i][tx] = src[(size_t)(k0 + i) * N + n0 + tx];
    __syncthreads();
#pragma unroll
    for (int i = threadIdx.y; i < 32; i += 8)
        dst[(size_t)(n0 + i) * K + k0 + tx] = __float2bfloat16(t[tx][i]);
}

__global__ void repack_kernel(const float* __restrict__ wq,
                              const float* __restrict__ wk,
                              const float* __restrict__ wv,
                              __nv_bfloat16* __restrict__ WT)
{
    int idx = blockIdx.x * 256 + threadIdx.x;   // idx = n*DD + d
    if (idx >= DD * QKV_N) return;
    int d = idx & (DD - 1);
    int n = idx >> 10;
    int sel = n >> 10;
    int nn  = n & 1023;
    int hh  = nn >> 6;
    int e   = nn & 63;
    const float* src = (sel == 0) ? wq : (sel == 1) ? wk : wv;
    WT[idx] = __float2bfloat16(src[((size_t)hh * DD + d) * HSZ + e]);
}

// ==================== LayerNorm (bf16 output) ==============================
__global__ void ln_kernel(const float* __restrict__ in,
                          const float* __restrict__ gg,
                          const float* __restrict__ bb,
                          __nv_bfloat16* __restrict__ out)
{
    int row = blockIdx.x;
    const float* x = in + (size_t)row * DD;
    float v[4];
    float s = 0.f, s2 = 0.f;
#pragma unroll
    for (int k = 0; k < 4; k++) {
        v[k] = x[threadIdx.x + k * 256];
        s  += v[k];
        s2 += v[k] * v[k];
    }
#pragma unroll
    for (int off = 16; off; off >>= 1) {
        s  += __shfl_xor_sync(0xffffffffu, s,  off);
        s2 += __shfl_xor_sync(0xffffffffu, s2, off);
    }
    __shared__ float red[2][8];
    int wid = threadIdx.x >> 5, lane = threadIdx.x & 31;
    if (lane == 0) { red[0][wid] = s; red[1][wid] = s2; }
    __syncthreads();
    float S = 0.f, S2 = 0.f;
#pragma unroll
    for (int w = 0; w < 8; w++) { S += red[0][w]; S2 += red[1][w]; }
    float mean = S * (1.0f / DD);
    float var  = S2 * (1.0f / DD) - mean * mean;
    float rstd = rsqrtf(var + 1e-5f);
    __nv_bfloat16* o = out + (size_t)row * DD;
#pragma unroll
    for (int k = 0; k < 4; k++) {
        int c = threadIdx.x + k * 256;
        o[c] = __float2bfloat16((v[k] - mean) * rstd * gg[c] + bb[c]);
    }
}

// ==================== BF16 GEMM: m16n8k16, 2-stage cp.async ================
// C[M,N] = A[M,K] @ BT[N,K]^T, A/BT bf16. Tile 128x128x32, 8 warps (2x4).
// Smem tile [128 rows][20 words] (16 data + 4 pad; bank = 20g+tig bijective).
// flags: 1=+bias(f32), 2=+res(f32), 4=relu, 8=bf16 output (else f32)
#define TILE_WORDS (128 * 20)
#define GEMM_SMEM_BYTES (4 * TILE_WORDS * 4)   // 2 stages x (A+B) = 40960 B

__global__ __launch_bounds__(256, 2)
void bf16gemm_kernel(int M, int N, int K,
                     const __nv_bfloat16* __restrict__ A,
                     const __nv_bfloat16* __restrict__ BT,
                     const float* __restrict__ bias,
                     const float* __restrict__ res,
                     void* __restrict__ Cv,
                     int flags)
{
    extern __shared__ __align__(16) uint32_t dsm[];
    // A stages at dsm[buf*TILE_WORDS], B stages at dsm[(2+buf)*TILE_WORDS]

    int tid  = threadIdx.x;
    int lane = tid & 31;
    int warp = tid >> 5;
    int g    = lane >> 2;
    int tig  = lane & 3;
    int warp_m = warp & 1;
    int warp_n = warp >> 1;
    int m0 = blockIdx.y * 128;
    int n0 = blockIdx.x * 128;

    float acc[4][4][4];
#pragma unroll
    for (int i = 0; i < 4; i++)
#pragma unroll
        for (int j = 0; j < 4; j++)
#pragma unroll
            for (int c = 0; c < 4; c++) acc[i][j][c] = 0.f;

    auto load_tiles = [&](int k0, int buf) {
        uint32_t* as = dsm + buf * TILE_WORDS;
        uint32_t* bs = dsm + (2 + buf) * TILE_WORDS;
        // 512 chunks (16B = 8 bf16) per tile; 2 per thread per tile
#pragma unroll
        for (int q = 0; q < 2; q++) {
            int ch = q * 256 + tid;
            int rr = ch >> 2, cc = ch & 3;
            cpasync16(s2u(as + rr * 20 + cc * 4),
                      A + (size_t)(m0 + rr) * K + k0 + cc * 8);
        }
#pragma unroll
        for (int q = 0; q < 2; q++) {
            int ch = q * 256 + tid;
            int rr = ch >> 2, cc = ch & 3;
            cpasync16(s2u(bs + rr * 20 + cc * 4),
                      BT + (size_t)(n0 + rr) * K + k0 + cc * 8);
        }
    };

    load_tiles(0, 0);
    asm volatile("cp.async.commit_group;\n");

    int nk = K / 32;
    for (int kt = 0; kt < nk; kt++) {
        int cur = kt & 1;
        if (kt + 1 < nk) {
            load_tiles((kt + 1) * 32, cur ^ 1);
            asm volatile("cp.async.commit_group;\n");
            asm volatile("cp.async.wait_group 1;\n");
        } else {
            asm volatile("cp.async.wait_group 0;\n");
        }
        __syncthreads();

        const uint32_t* As = dsm + cur * TILE_WORDS;
        const uint32_t* Bs = dsm + (2 + cur) * TILE_WORDS;
#pragma unroll
        for (int s = 0; s < 2; s++) {
            int kw = s * 8;
            uint32_t afr[4][4], bfr[4][2];
#pragma unroll
            for (int i = 0; i < 4; i++) {
                int r = warp_m * 64 + i * 16 + g;
                afr[i][0] = As[r * 20 + kw + tig];
                afr[i][1] = As[(r + 8) * 20 + kw + tig];
                afr[i][2] = As[r * 20 + kw + tig + 4];
                afr[i][3] = As[(r + 8) * 20 + kw + tig + 4];
            }
#pragma unroll
            for (int j = 0; j < 4; j++) {
                int n = warp_n * 32 + j * 8 + g;
                bfr[j][0] = Bs[n * 20 + kw + tig];
                bfr[j][1] = Bs[n * 20 + kw + tig + 4];
            }
#pragma unroll
            for (int i = 0; i < 4; i++)
#pragma unroll
                for (int j = 0; j < 4; j++)
                    mma_bf16(acc[i][j], afr[i], bfr[j]);
        }
        __syncthreads();
    }

    // ---- epilogue (direct store) ----
    bool outbf = (flags & 8) != 0;
#pragma unroll
    for (int j = 0; j < 4; j++) {
        int col = n0 + warp_n * 32 + j * 8 + 2 * tig;
        float b0 = 0.f, b1 = 0.f;
        if (flags & 1) { b0 = bias[col]; b1 = bias[col + 1]; }
#pragma unroll
        for (int i = 0; i < 4; i++) {
            int rr = m0 + warp_m * 64 + i * 16 + g;
#pragma unroll
            for (int half = 0; half < 2; half++) {
                int row = rr + half * 8;
                size_t base = (size_t)row * N + col;
                float v0 = acc[i][j][half * 2 + 0] + b0;
                float v1 = acc[i][j][half * 2 + 1] + b1;
                if (flags & 2) {
                    float2 rv = *(const float2*)(res + base);
                    v0 += rv.x; v1 += rv.y;
                }
                if (flags & 4) { v0 = fmaxf(v0, 0.f); v1 = fmaxf(v1, 0.f); }
                if (outbf) {
                    *(uint32_t*)((__nv_bfloat16*)Cv + base) = f2bfpair(v0, v1);
                } else {
                    *(float2*)((float*)Cv + base) = make_float2(v0, v1);
                }
            }
        }
    }
}

// ==================== TF32 flash attention (bf16 qkv in, bf16 o out) =======
#define ATT_SMEM_BYTES ((128*68 + 128*68 + 64*72) * 4)

__global__ __launch_bounds__(256, 2)
void attn_tc_kernel(const __nv_bfloat16* __restrict__ qkv,
                    __nv_bfloat16* __restrict__ O)
{
    extern __shared__ uint32_t sm[];
    uint32_t* Qs = sm;                   // [128][68] fp32(tf32-exact)
    uint32_t* KP = sm + 128 * 68;        // Ks[64][68] / Ps[128][68]
    uint32_t* Vs = sm + 2 * 128 * 68;    // [64][72]

    int b  = blockIdx.z;
    int h  = blockIdx.y;
    int q0 = blockIdx.x * 128;
    int tid  = threadIdx.x;
    int lane = tid & 31, warp = tid >> 5;
    int g    = lane >> 2, tig = lane & 3;

    // ---- load Q tile (128x64 bf16 -> fp32) ----
    {
        int r  = tid >> 1;
        int c0 = (tid & 1) * 32;
        const __nv_bfloat16* src =
            qkv + (size_t)(b * SS + q0 + r) * QKV_N + h * HSZ + c0;
#pragma unroll
        for (int q = 0; q < 4; q++) {
            uint4 raw = *(const uint4*)(src + q * 8);   // 8 bf16
            float2 f0 = bf2f(raw.x), f1 = bf2f(raw.y);
            float2 f2 = bf2f(raw.z), f3 = bf2f(raw.w);
            float* d = (float*)&Qs[r * 68 + c0 + q * 8];
            *(float4*)(d)     = make_float4(f0.x, f0.y, f1.x, f1.y);
            *(float4*)(d + 4) = make_float4(f2.x, f2.y, f3.x, f3.y);
        }
    }

    float o_[8][4];
#pragma unroll
    for (int n = 0; n < 8; n++)
#pragma unroll
        for (int c = 0; c < 4; c++) o_[n][c] = 0.f;
    float m0 = -1e30f, m8 = -1e30f, l0 = 0.f, l8 = 0.f;

    int Rw   = q0 + warp * 16;
    int row0 = Rw + g;
    int rmax = Rw + 15;
    int rloc = warp * 16 + g;

    int ntile = 2 * blockIdx.x + 2;
    for (int jt = 0; jt < ntile; jt++) {
        int j0 = jt * 64;
        __syncthreads();
        // ---- load K,V tiles (64x64 bf16 -> fp32) ----
        {
            int t  = tid >> 2;
            int c0 = (tid & 3) * 16;
            const __nv_bfloat16* kp =
                qkv + (size_t)(b * SS + j0 + t) * QKV_N + DD + h * HSZ + c0;
#pragma unroll
            for (int q = 0; q < 2; q++) {
                uint4 kr = *(const uint4*)(kp + q * 8);
                float2 f0 = bf2f(kr.x), f1 = bf2f(kr.y);
                float2 f2 = bf2f(kr.z), f3 = bf2f(kr.w);
                float* dk = (float*)&KP[t * 68 + c0 + q * 8];
                *(float4*)(dk)     = make_float4(f0.x, f0.y, f1.x, f1.y);
                *(float4*)(dk + 4) = make_float4(f2.x, f2.y, f3.x, f3.y);
                uint4 vr = *(const uint4*)(kp + DD + q * 8);
                f0 = bf2f(vr.x); f1 = bf2f(vr.y);
                f2 = bf2f(vr.z); f3 = bf2f(vr.w);
                float* dv = (float*)&Vs[t * 72 + c0 + q * 8];
                *(float4*)(dv)     = make_float4(f0.x, f0.y, f1.x, f1.y);
                *(float4*)(dv + 4) = make_float4(f2.x, f2.y, f3.x, f3.y);
            }
        }
        __syncthreads();

        bool active = (j0 <= rmax);
        float p[8][4];
        if (active) {
#pragma unroll
            for (int n = 0; n < 8; n++)
#pragma unroll
                for (int c = 0; c < 4; c++) p[n][c] = 0.f;
#pragma unroll
            for (int ks = 0; ks < 8; ks++) {
                int kb = ks * 8;
                uint32_t a[4];
                a[0] = Qs[rloc * 68 + kb + tig];
                a[1] = Qs[(rloc + 8) * 68 + kb + tig];
                a[2] = Qs[rloc * 68 + kb + tig + 4];
                a[3] = Qs[(rloc + 8) * 68 + kb + tig + 4];
#pragma unroll
                for (int n = 0; n < 8; n++) {
                    uint32_t bf[2];
                    bf[0] = KP[(n * 8 + g) * 68 + kb + tig];
                    bf[1] = KP[(n * 8 + g) * 68 + kb + tig + 4];
                    mma_tf32(p[n], a, bf);
                }
            }
            bool needmask = (j0 + 63 > Rw);
            float mt0 = -1e30f, mt8 = -1e30f;
#pragma unroll
            for (int n = 0; n < 8; n++) {
#pragma unroll
                for (int c = 0; c < 4; c++) {
                    float v = p[n][c] * 0.125f;
                    if (needmask) {
                        int col = j0 + n * 8 + 2 * tig + (c & 1);
                        int row = row0 + (c >> 1) * 8;
                        if (col > row) v = -1e30f;
                    }
                    p[n][c] = v;
                    if (c < 2) mt0 = fmaxf(mt0, v); else mt8 = fmaxf(mt8, v);
                }
            }
            mt0 = fmaxf(mt0, __shfl_xor_sync(0xffffffffu, mt0, 1));
            mt0 = fmaxf(mt0, __shfl_xor_sync(0xffffffffu, mt0, 2));
            mt8 = fmaxf(mt8, __shfl_xor_sync(0xffffffffu, mt8, 1));
            mt8 = fmaxf(mt8, __shfl_xor_sync(0xffffffffu, mt8, 2));
            float nm0 = fmaxf(m0, mt0), nm8 = fmaxf(m8, mt8);
            float al0 = __expf(m0 - nm0), al8 = __expf(m8 - nm8);
            m0 = nm0; m8 = nm8;
            float ps0 = 0.f, ps8 = 0.f;
#pragma unroll
            for (int n = 0; n < 8; n++) {
                p[n][0] = __expf(p[n][0] - nm0);
                p[n][1] = __expf(p[n][1] - nm0);
                p[n][2] = __expf(p[n][2] - nm8);
                p[n][3] = __expf(p[n][3] - nm8);
                ps0 += p[n][0] + p[n][1];
                ps8 += p[n][2] + p[n][3];
            }
            ps0 += __shfl_xor_sync(0xffffffffu, ps0, 1);
            ps0 += __shfl_xor_sync(0xffffffffu, ps0, 2);
            ps8 += __shfl_xor_sync(0xffffffffu, ps8, 1);
            ps8 += __shfl_xor_sync(0xffffffffu, ps8, 2);
            l0 = l0 * al0 + ps0;
            l8 = l8 * al8 + ps8;
#pragma unroll
            for (int n = 0; n < 8; n++) {
                o_[n][0] *= al0; o_[n][1] *= al0;
                o_[n][2] *= al8; o_[n][3] *= al8;
            }
        }
        __syncthreads();

        if (active) {
#pragma unroll
            for (int n = 0; n < 8; n++) {
                uint2 lo = make_uint2(f2tf32(p[n][0]), f2tf32(p[n][1]));
                uint2 hi = make_uint2(f2tf32(p[n][2]), f2tf32(p[n][3]));
                *(uint2*)&KP[rloc * 68 + n * 8 + 2 * tig] = lo;
                *(uint2*)&KP[(rloc + 8) * 68 + n * 8 + 2 * tig] = hi;
            }
#pragma unroll
            for (int ks = 0; ks < 8; ks++) {
                int kb = ks * 8;
                uint32_t a[4];
                a[0] = KP[rloc * 68 + kb + tig];
                a[1] = KP[(rloc + 8) * 68 + kb + tig];
                a[2] = KP[rloc * 68 + kb + tig + 4];
                a[3] = KP[(rloc + 8) * 68 + kb + tig + 4];
#pragma unroll
                for (int n = 0; n < 8; n++) {
                    uint32_t bf[2];
                    bf[0] = Vs[(kb + tig) * 72 + n * 8 + g];
                    bf[1] = Vs[(kb + tig + 4) * 72 + n * 8 + g];
                    mma_tf32(o_[n], a, bf);
                }
            }
        }
    }

    // ---- finalize + write O as bf16 (proj GEMM A operand) ----
    float inv0 = 1.0f / l0, inv8 = 1.0f / l8;
    size_t base0 = (size_t)(b * SS + q0 + rloc) * DD + h * HSZ;
    size_t base8 = base0 + 8 * DD;
#pragma unroll
    for (int n = 0; n < 8; n++) {
        int col = n * 8 + 2 * tig;
        *(uint32_t*)(O + base0 + col) = f2bfpair(o_[n][0] * inv0, o_[n][1] * inv0);
        *(uint32_t*)(O + base8 + col) = f2bfpair(o_[n][2] * inv8, o_[n][3] * inv8);
    }
}

// ==================== host launcher ========================================
extern "C" void kernel_launch(void* const* d_in, const int* in_sizes, int n_in,
                              void* d_out, int out_size)
{
    const float* x      = (const float*)d_in[0];
    const float* wq     = (const float*)d_in[1];
    const float* wk     = (const float*)d_in[2];
    const float* wv     = (const float*)d_in[3];
    const float* proj_w = (const float*)d_in[4];
    const float* proj_b = (const float*)d_in[5];
    const float* ff1_w  = (const float*)d_in[6];
    const float* ff1_b  = (const float*)d_in[7];
    const float* ff2_w  = (const float*)d_in[8];
    const float* ff2_b  = (const float*)d_in[9];
    const float* ln1_g  = (const float*)d_in[10];
    const float* ln1_b  = (const float*)d_in[11];
    const float* ln2_g  = (const float*)d_in[12];
    const float* ln2_b  = (const float*)d_in[13];
    float* out = (float*)d_out;

    static __nv_bfloat16 *h = nullptr, *qkv, *wpack, *o, *ffh,
                         *wproj, *wff1, *wff2;
    if (!h) {
        cudaGetSymbolAddress((void**)&h,     g_h);
        cudaGetSymbolAddress((void**)&qkv,   g_qkv);
        cudaGetSymbolAddress((void**)&wpack, g_wqkv);
        cudaGetSymbolAddress((void**)&o,     g_o);
        cudaGetSymbolAddress((void**)&ffh,   g_ffh);
        cudaGetSymbolAddress((void**)&wproj, g_wproj);
        cudaGetSymbolAddress((void**)&wff1,  g_wff1);
        cudaGetSymbolAddress((void**)&wff2,  g_wff2);
        cudaFuncSetAttribute(attn_tc_kernel,
                             cudaFuncAttributeMaxDynamicSharedMemorySize,
                             ATT_SMEM_BYTES);
        cudaFuncSetAttribute(bf16gemm_kernel,
                             cudaFuncAttributeMaxDynamicSharedMemorySize,
                             GEMM_SMEM_BYTES);
    }

    // 0. weight prep: transposed + bf16-rounded copies
    repack_kernel<<<(DD * QKV_N + 255) / 256, 256>>>(wq, wk, wv, wpack);
    transpose_round_kernel<<<dim3(DD / 32, DD / 32),  dim3(32, 8)>>>(proj_w, wproj, DD,  DD);
    transpose_round_kernel<<<dim3(DFF / 32, DD / 32), dim3(32, 8)>>>(ff1_w,  wff1,  DD,  DFF);
    transpose_round_kernel<<<dim3(DD / 32, DFF / 32), dim3(32, 8)>>>(ff2_w,  wff2,  DFF, DD);
    // 1. h = LN1(x)  (bf16)
    ln_kernel<<<NROWS, 256>>>(x, ln1_g, ln1_b, h);
    // 2. qkv = h @ Wqkv  (bf16 output)
    bf16gemm_kernel<<<dim3(QKV_N / 128, NROWS / 128), 256, GEMM_SMEM_BYTES>>>(
        NROWS, QKV_N, DD, h, wpack, nullptr, nullptr, qkv, 8);
    // 3. flash attention -> o (bf16)
    attn_tc_kernel<<<dim3(SS / 128, HH, BB), 256, ATT_SMEM_BYTES>>>(qkv, o);
    // 4. out = x + o @ proj_w + proj_b  (f32 output)
    bf16gemm_kernel<<<dim3(DD / 128, NROWS / 128), 256, GEMM_SMEM_BYTES>>>(
        NROWS, DD, DD, o, wproj, proj_b, x, out, 1 | 2);
    // 5. h = LN2(out)  (bf16)
    ln_kernel<<<NROWS, 256>>>(out, ln2_g, ln2_b, h);
    // 6. ffh = relu(h @ ff1_w + ff1_b)  (bf16 output)
    bf16gemm_kernel<<<dim3(DFF / 128, NROWS / 128), 256, GEMM_SMEM_BYTES>>>(
        NROWS, DFF, DD, h, wff1, ff1_b, nullptr, ffh, 1 | 4 | 8);
    // 7. out += ffh @ ff2_w + ff2_b  (f32 output)
    bf16gemm_kernel<<<dim3(DD / 128, NROWS / 128), 256, GEMM_SMEM_BYTES>>>(
        NROWS, DD, DFF, ffh, wff2, ff2_b, out, out, 1 | 2);
}

// round 14
// speedup vs baseline: 1.8620x; 1.1592x over previous
#include <cuda_runtime.h>
#include <cuda_bf16.h>
#include <math.h>
#include <stdint.h>

// ---------------- problem constants ----------------
#define BB 4
#define SS 2048
#define DD 1024
#define HH 16
#define HSZ 64
#define DFF 4096
#define NROWS (BB * SS)          // 8192
#define QKV_N (3 * DD)           // 3072

// ---------------- scratch (bf16 activations/weights) -----------------------
__device__ __nv_bfloat16 g_h[NROWS * DD];        // LN output
__device__ __nv_bfloat16 g_qkv[NROWS * QKV_N];   // Q|K|V head-concat
__device__ __nv_bfloat16 g_wqkv[QKV_N * DD];     // qkv weights T [n][d]
__device__ __nv_bfloat16 g_o[NROWS * DD];        // attention output
__device__ __nv_bfloat16 g_ffh[NROWS * DFF];     // FFN hidden
__device__ __nv_bfloat16 g_wproj[DD * DD];       // proj_w T [n][k]
__device__ __nv_bfloat16 g_wff1[DFF * DD];       // ff1_w T [n][k]
__device__ __nv_bfloat16 g_wff2[DD * DFF];       // ff2_w T [n][k]

// ==================== helpers ==============================================
__device__ __forceinline__ void mma_bf16(float* c, const uint32_t* a,
                                         const uint32_t* b) {
    asm volatile(
        "mma.sync.aligned.m16n8k16.row.col.f32.bf16.bf16.f32 "
        "{%0,%1,%2,%3}, {%4,%5,%6,%7}, {%8,%9}, {%0,%1,%2,%3};\n"
        : "+f"(c[0]), "+f"(c[1]), "+f"(c[2]), "+f"(c[3])
        : "r"(a[0]), "r"(a[1]), "r"(a[2]), "r"(a[3]),
          "r"(b[0]), "r"(b[1]));
}
__device__ __forceinline__ uint32_t s2u(const void* p) {
    return (uint32_t)__cvta_generic_to_shared(p);
}
__device__ __forceinline__ void cpasync16(uint32_t dst, const void* src) {
    asm volatile("cp.async.ca.shared.global [%0], [%1], 16;\n"
                 :: "r"(dst), "l"(src));
}
__device__ __forceinline__ uint32_t f2bfpair(float a, float b) {
    __nv_bfloat162 h = __floats2bfloat162_rn(a, b);
    return *reinterpret_cast<uint32_t*>(&h);
}
#define LDMX4T(r0, r1, r2, r3, addr) \
    asm volatile("ldmatrix.sync.aligned.m8n8.x4.trans.shared.b16 {%0,%1,%2,%3}, [%4];" \
                 : "=r"(r0), "=r"(r1), "=r"(r2), "=r"(r3) : "r"(addr))

// ==================== weight prep ==========================================
__global__ void transpose_round_kernel(const float* __restrict__ src,
                                       __nv_bfloat16* __restrict__ dst,
                                       int K, int N)
{
    __shared__ float t[32][33];
    int n0 = blockIdx.x * 32, k0 = blockIdx.y * 32;
    int tx = threadIdx.x;
#pragma unroll
    for (int i = threadIdx.y; i < 32; i += 8)
        t[i][tx] = src[(size_t)(k0 + i) * N + n0 + tx];
    __syncthreads();
#pragma unroll
    for (int i = threadIdx.y; i < 32; i += 8)
        dst[(size_t)(n0 + i) * K + k0 + tx] = __float2bfloat16(t[tx][i]);
}

__global__ void repack_kernel(const float* __restrict__ wq,
                              const float* __restrict__ wk,
                              const float* __restrict__ wv,
                              __nv_bfloat16* __restrict__ WT)
{
    int idx = blockIdx.x * 256 + threadIdx.x;   // idx = n*DD + d
    if (idx >= DD * QKV_N) return;
    int d = idx & (DD - 1);
    int n = idx >> 10;
    int sel = n >> 10;
    int nn  = n & 1023;
    int hh  = nn >> 6;
    int e   = nn & 63;
    const float* src = (sel == 0) ? wq : (sel == 1) ? wk : wv;
    WT[idx] = __float2bfloat16(src[((size_t)hh * DD + d) * HSZ + e]);
}

// ==================== LayerNorm (bf16 output) ==============================
__global__ void ln_kernel(const float* __restrict__ in,
                          const float* __restrict__ gg,
                          const float* __restrict__ bb,
                          __nv_bfloat16* __restrict__ out)
{
    int row = blockIdx.x;
    const float* x = in + (size_t)row * DD;
    float v[4];
    float s = 0.f, s2 = 0.f;
#pragma unroll
    for (int k = 0; k < 4; k++) {
        v[k] = x[threadIdx.x + k * 256];
        s  += v[k];
        s2 += v[k] * v[k];
    }
#pragma unroll
    for (int off = 16; off; off >>= 1) {
        s  += __shfl_xor_sync(0xffffffffu, s,  off);
        s2 += __shfl_xor_sync(0xffffffffu, s2, off);
    }
    __shared__ float red[2][8];
    int wid = threadIdx.x >> 5, lane = threadIdx.x & 31;
    if (lane == 0) { red[0][wid] = s; red[1][wid] = s2; }
    __syncthreads();
    float S = 0.f, S2 = 0.f;
#pragma unroll
    for (int w = 0; w < 8; w++) { S += red[0][w]; S2 += red[1][w]; }
    float mean = S * (1.0f / DD);
    float var  = S2 * (1.0f / DD) - mean * mean;
    float rstd = rsqrtf(var + 1e-5f);
    __nv_bfloat16* o = out + (size_t)row * DD;
#pragma unroll
    for (int k = 0; k < 4; k++) {
        int c = threadIdx.x + k * 256;
        o[c] = __float2bfloat16((v[k] - mean) * rstd * gg[c] + bb[c]);
    }
}

// ==================== BF16 GEMM: m16n8k16, 2-stage cp.async ================
#define TILE_WORDS (128 * 20)
#define GEMM_SMEM_BYTES (4 * TILE_WORDS * 4)

__global__ __launch_bounds__(256, 2)
void bf16gemm_kernel(int M, int N, int K,
                     const __nv_bfloat16* __restrict__ A,
                     const __nv_bfloat16* __restrict__ BT,
                     const float* __restrict__ bias,
                     const float* __restrict__ res,
                     void* __restrict__ Cv,
                     int flags)
{
    extern __shared__ __align__(16) uint32_t dsm[];

    int tid  = threadIdx.x;
    int lane = tid & 31;
    int warp = tid >> 5;
    int g    = lane >> 2;
    int tig  = lane & 3;
    int warp_m = warp & 1;
    int warp_n = warp >> 1;
    int m0 = blockIdx.y * 128;
    int n0 = blockIdx.x * 128;

    float acc[4][4][4];
#pragma unroll
    for (int i = 0; i < 4; i++)
#pragma unroll
        for (int j = 0; j < 4; j++)
#pragma unroll
            for (int c = 0; c < 4; c++) acc[i][j][c] = 0.f;

    auto load_tiles = [&](int k0, int buf) {
        uint32_t* as = dsm + buf * TILE_WORDS;
        uint32_t* bs = dsm + (2 + buf) * TILE_WORDS;
#pragma unroll
        for (int q = 0; q < 2; q++) {
            int ch = q * 256 + tid;
            int rr = ch >> 2, cc = ch & 3;
            cpasync16(s2u(as + rr * 20 + cc * 4),
                      A + (size_t)(m0 + rr) * K + k0 + cc * 8);
        }
#pragma unroll
        for (int q = 0; q < 2; q++) {
            int ch = q * 256 + tid;
            int rr = ch >> 2, cc = ch & 3;
            cpasync16(s2u(bs + rr * 20 + cc * 4),
                      BT + (size_t)(n0 + rr) * K + k0 + cc * 8);
        }
    };

    load_tiles(0, 0);
    asm volatile("cp.async.commit_group;\n");

    int nk = K / 32;
    for (int kt = 0; kt < nk; kt++) {
        int cur = kt & 1;
        if (kt + 1 < nk) {
            load_tiles((kt + 1) * 32, cur ^ 1);
            asm volatile("cp.async.commit_group;\n");
            asm volatile("cp.async.wait_group 1;\n");
        } else {
            asm volatile("cp.async.wait_group 0;\n");
        }
        __syncthreads();

        const uint32_t* As = dsm + cur * TILE_WORDS;
        const uint32_t* Bs = dsm + (2 + cur) * TILE_WORDS;
#pragma unroll
        for (int s = 0; s < 2; s++) {
            int kw = s * 8;
            uint32_t afr[4][4], bfr[4][2];
#pragma unroll
            for (int i = 0; i < 4; i++) {
                int r = warp_m * 64 + i * 16 + g;
                afr[i][0] = As[r * 20 + kw + tig];
                afr[i][1] = As[(r + 8) * 20 + kw + tig];
                afr[i][2] = As[r * 20 + kw + tig + 4];
                afr[i][3] = As[(r + 8) * 20 + kw + tig + 4];
            }
#pragma unroll
            for (int j = 0; j < 4; j++) {
                int n = warp_n * 32 + j * 8 + g;
                bfr[j][0] = Bs[n * 20 + kw + tig];
                bfr[j][1] = Bs[n * 20 + kw + tig + 4];
            }
#pragma unroll
            for (int i = 0; i < 4; i++)
#pragma unroll
                for (int j = 0; j < 4; j++)
                    mma_bf16(acc[i][j], afr[i], bfr[j]);
        }
        __syncthreads();
    }

    bool outbf = (flags & 8) != 0;
#pragma unroll
    for (int j = 0; j < 4; j++) {
        int col = n0 + warp_n * 32 + j * 8 + 2 * tig;
        float b0 = 0.f, b1 = 0.f;
        if (flags & 1) { b0 = bias[col]; b1 = bias[col + 1]; }
#pragma unroll
        for (int i = 0; i < 4; i++) {
            int rr = m0 + warp_m * 64 + i * 16 + g;
#pragma unroll
            for (int half = 0; half < 2; half++) {
                int row = rr + half * 8;
                size_t base = (size_t)row * N + col;
                float v0 = acc[i][j][half * 2 + 0] + b0;
                float v1 = acc[i][j][half * 2 + 1] + b1;
                if (flags & 2) {
                    float2 rv = *(const float2*)(res + base);
                    v0 += rv.x; v1 += rv.y;
                }
                if (flags & 4) { v0 = fmaxf(v0, 0.f); v1 = fmaxf(v1, 0.f); }
                if (outbf) {
                    *(uint32_t*)((__nv_bfloat16*)Cv + base) = f2bfpair(v0, v1);
                } else {
                    *(float2*)((float*)Cv + base) = make_float2(v0, v1);
                }
            }
        }
    }
}

// ==================== Full-BF16 flash attention ============================
// All tiles bf16, stride 36 uint32 words (32 data + 4 pad).
//   Qs [128][36w]  KPs: Ks[64][36w] phase1 / Ps[128][36w] phase2  Vs [64][36w]
#define ATT_SMEM_BYTES ((128*36 + 128*36 + 64*36) * 4)   // 46080

__global__ __launch_bounds__(256, 2)
void attn_tc_kernel(const __nv_bfloat16* __restrict__ qkv,
                    __nv_bfloat16* __restrict__ O)
{
    extern __shared__ uint32_t sm[];
    uint32_t* Qs  = sm;                  // [128][36]
    uint32_t* KPs = sm + 128 * 36;       // Ks[64][36] / Ps[128][36]
    uint32_t* Vs  = sm + 256 * 36;       // [64][36]

    int b  = blockIdx.z;
    int h  = blockIdx.y;
    int q0 = blockIdx.x * 128;
    int tid  = threadIdx.x;
    int lane = tid & 31, warp = tid >> 5;
    int g    = lane >> 2, tig = lane & 3;

    // ---- load Q tile raw (128 rows x 8 chunks of 16B) ----
#pragma unroll
    for (int q = 0; q < 4; q++) {
        int ch = q * 256 + tid;
        int r = ch >> 3, c4 = ch & 7;
        *(uint4*)&Qs[r * 36 + c4 * 4] =
            *(const uint4*)(qkv + (size_t)(b * SS + q0 + r) * QKV_N + h * HSZ + c4 * 8);
    }

    float o_[8][4];
#pragma unroll
    for (int n = 0; n < 8; n++)
#pragma unroll
        for (int c = 0; c < 4; c++) o_[n][c] = 0.f;
    float m0 = -1e30f, m8 = -1e30f, l0 = 0.f, l8 = 0.f;

    int Rw   = q0 + warp * 16;
    int row0 = Rw + g;
    int rmax = Rw + 15;
    int rloc = warp * 16 + g;

    // ldmatrix.trans per-lane base for V (n-word offset added per jp)
    int vmrow_base = ((lane >> 3) & 1) * 8 + (lane & 7);
    int vnw = (lane >> 4) * 4;

    int ntile = 2 * blockIdx.x + 2;
    for (int jt = 0; jt < ntile; jt++) {
        int j0 = jt * 64;
        __syncthreads();
        // ---- load K,V tiles raw (64 rows x 8 chunks each) ----
#pragma unroll
        for (int q = 0; q < 2; q++) {
            int ch = q * 256 + tid;
            int t = ch >> 3, c4 = ch & 7;
            const __nv_bfloat16* kp =
                qkv + (size_t)(b * SS + j0 + t) * QKV_N + DD + h * HSZ + c4 * 8;
            *(uint4*)&KPs[t * 36 + c4 * 4] = *(const uint4*)kp;
            *(uint4*)&Vs[t * 36 + c4 * 4]  = *(const uint4*)(kp + DD);
        }
        __syncthreads();

        bool active = (j0 <= rmax);
        float p[8][4];
        if (active) {
            // ---- S = Q K^T, bf16 m16n8k16 ----
#pragma unroll
            for (int n = 0; n < 8; n++)
#pragma unroll
                for (int c = 0; c < 4; c++) p[n][c] = 0.f;
#pragma unroll
            for (int ks = 0; ks < 4; ks++) {
                int kw = ks * 8;
                uint32_t a[4];
                a[0] = Qs[rloc * 36 + kw + tig];
                a[1] = Qs[(rloc + 8) * 36 + kw + tig];
                a[2] = Qs[rloc * 36 + kw + tig + 4];
                a[3] = Qs[(rloc + 8) * 36 + kw + tig + 4];
#pragma unroll
                for (int n = 0; n < 8; n++) {
                    uint32_t bf[2];
                    bf[0] = KPs[(n * 8 + g) * 36 + kw + tig];
                    bf[1] = KPs[(n * 8 + g) * 36 + kw + tig + 4];
                    mma_bf16(p[n], a, bf);
                }
            }
            // ---- scale + mask + online softmax ----
            bool needmask = (j0 + 63 > Rw);
            float mt0 = -1e30f, mt8 = -1e30f;
#pragma unroll
            for (int n = 0; n < 8; n++) {
#pragma unroll
                for (int c = 0; c < 4; c++) {
                    float v = p[n][c] * 0.125f;
                    if (needmask) {
                        int col = j0 + n * 8 + 2 * tig + (c & 1);
                        int row = row0 + (c >> 1) * 8;
                        if (col > row) v = -1e30f;
                    }
                    p[n][c] = v;
                    if (c < 2) mt0 = fmaxf(mt0, v); else mt8 = fmaxf(mt8, v);
                }
            }
            mt0 = fmaxf(mt0, __shfl_xor_sync(0xffffffffu, mt0, 1));
            mt0 = fmaxf(mt0, __shfl_xor_sync(0xffffffffu, mt0, 2));
            mt8 = fmaxf(mt8, __shfl_xor_sync(0xffffffffu, mt8, 1));
            mt8 = fmaxf(mt8, __shfl_xor_sync(0xffffffffu, mt8, 2));
            float nm0 = fmaxf(m0, mt0), nm8 = fmaxf(m8, mt8);
            float al0 = __expf(m0 - nm0), al8 = __expf(m8 - nm8);
            m0 = nm0; m8 = nm8;
            float ps0 = 0.f, ps8 = 0.f;
#pragma unroll
            for (int n = 0; n < 8; n++) {
                p[n][0] = __expf(p[n][0] - nm0);
                p[n][1] = __expf(p[n][1] - nm0);
                p[n][2] = __expf(p[n][2] - nm8);
                p[n][3] = __expf(p[n][3] - nm8);
                ps0 += p[n][0] + p[n][1];
                ps8 += p[n][2] + p[n][3];
            }
            ps0 += __shfl_xor_sync(0xffffffffu, ps0, 1);
            ps0 += __shfl_xor_sync(0xffffffffu, ps0, 2);
            ps8 += __shfl_xor_sync(0xffffffffu, ps8, 1);
            ps8 += __shfl_xor_sync(0xffffffffu, ps8, 2);
            l0 = l0 * al0 + ps0;
            l8 = l8 * al8 + ps8;
#pragma unroll
            for (int n = 0; n < 8; n++) {
                o_[n][0] *= al0; o_[n][1] *= al0;
                o_[n][2] *= al8; o_[n][3] *= al8;
            }
        }
        __syncthreads();             // Ks reads done; KPs becomes Ps

        if (active) {
            // ---- write P as bf16 pairs (own rows only) ----
#pragma unroll
            for (int n = 0; n < 8; n++) {
                KPs[rloc * 36 + n * 4 + tig]       = f2bfpair(p[n][0], p[n][1]);
                KPs[(rloc + 8) * 36 + n * 4 + tig] = f2bfpair(p[n][2], p[n][3]);
            }
            // ---- O += P V, bf16; V frags via ldmatrix.trans ----
#pragma unroll
            for (int ks = 0; ks < 4; ks++) {
                int kw = ks * 8;
                uint32_t a[4];
                a[0] = KPs[rloc * 36 + kw + tig];
                a[1] = KPs[(rloc + 8) * 36 + kw + tig];
                a[2] = KPs[rloc * 36 + kw + tig + 4];
                a[3] = KPs[(rloc + 8) * 36 + kw + tig + 4];
                int mrow = ks * 16 + vmrow_base;
#pragma unroll
                for (int jp = 0; jp < 4; jp++) {
                    uint32_t r0, r1, r2, r3;
                    uint32_t addr = s2u(&Vs[mrow * 36 + jp * 8 + vnw]);
                    LDMX4T(r0, r1, r2, r3, addr);
                    uint32_t bfa[2] = {r0, r1}, bfb[2] = {r2, r3};
                    mma_bf16(o_[jp * 2],     a, bfa);
                    mma_bf16(o_[jp * 2 + 1], a, bfb);
                }
            }
        }
    }

    // ---- finalize + write O as bf16 ----
    float inv0 = 1.0f / l0, inv8 = 1.0f / l8;
    size_t base0 = (size_t)(b * SS + q0 + rloc) * DD + h * HSZ;
    size_t base8 = base0 + 8 * DD;
#pragma unroll
    for (int n = 0; n < 8; n++) {
        int col = n * 8 + 2 * tig;
        *(uint32_t*)(O + base0 + col) = f2bfpair(o_[n][0] * inv0, o_[n][1] * inv0);
        *(uint32_t*)(O + base8 + col) = f2bfpair(o_[n][2] * inv8, o_[n][3] * inv8);
    }
}

// ==================== host launcher ========================================
extern "C" void kernel_launch(void* const* d_in, const int* in_sizes, int n_in,
                              void* d_out, int out_size)
{
    const float* x      = (const float*)d_in[0];
    const float* wq     = (const float*)d_in[1];
    const float* wk     = (const float*)d_in[2];
    const float* wv     = (const float*)d_in[3];
    const float* proj_w = (const float*)d_in[4];
    const float* proj_b = (const float*)d_in[5];
    const float* ff1_w  = (const float*)d_in[6];
    const float* ff1_b  = (const float*)d_in[7];
    const float* ff2_w  = (const float*)d_in[8];
    const float* ff2_b  = (const float*)d_in[9];
    const float* ln1_g  = (const float*)d_in[10];
    const float* ln1_b  = (const float*)d_in[11];
    const float* ln2_g  = (const float*)d_in[12];
    const float* ln2_b  = (const float*)d_in[13];
    float* out = (float*)d_out;

    static __nv_bfloat16 *h = nullptr, *qkv, *wpack, *o, *ffh,
                         *wproj, *wff1, *wff2;
    if (!h) {
        cudaGetSymbolAddress((void**)&h,     g_h);
        cudaGetSymbolAddress((void**)&qkv,   g_qkv);
        cudaGetSymbolAddress((void**)&wpack, g_wqkv);
        cudaGetSymbolAddress((void**)&o,     g_o);
        cudaGetSymbolAddress((void**)&ffh,   g_ffh);
        cudaGetSymbolAddress((void**)&wproj, g_wproj);
        cudaGetSymbolAddress((void**)&wff1,  g_wff1);
        cudaGetSymbolAddress((void**)&wff2,  g_wff2);
        cudaFuncSetAttribute(attn_tc_kernel,
                             cudaFuncAttributeMaxDynamicSharedMemorySize,
                             ATT_SMEM_BYTES);
        cudaFuncSetAttribute(bf16gemm_kernel,
                             cudaFuncAttributeMaxDynamicSharedMemorySize,
                             GEMM_SMEM_BYTES);
    }

    // 0. weight prep
    repack_kernel<<<(DD * QKV_N + 255) / 256, 256>>>(wq, wk, wv, wpack);
    transpose_round_kernel<<<dim3(DD / 32, DD / 32),  dim3(32, 8)>>>(proj_w, wproj, DD,  DD);
    transpose_round_kernel<<<dim3(DFF / 32, DD / 32), dim3(32, 8)>>>(ff1_w,  wff1,  DD,  DFF);
    transpose_round_kernel<<<dim3(DD / 32, DFF / 32), dim3(32, 8)>>>(ff2_w,  wff2,  DFF, DD);
    // 1. h = LN1(x)
    ln_kernel<<<NROWS, 256>>>(x, ln1_g, ln1_b, h);
    // 2. qkv = h @ Wqkv  (bf16 out)
    bf16gemm_kernel<<<dim3(QKV_N / 128, NROWS / 128), 256, GEMM_SMEM_BYTES>>>(
        NROWS, QKV_N, DD, h, wpack, nullptr, nullptr, qkv, 8);
    // 3. flash attention -> o (bf16)
    attn_tc_kernel<<<dim3(SS / 128, HH, BB), 256, ATT_SMEM_BYTES>>>(qkv, o);
    // 4. out = x + o @ proj_w + proj_b
    bf16gemm_kernel<<<dim3(DD / 128, NROWS / 128), 256, GEMM_SMEM_BYTES>>>(
        NROWS, DD, DD, o, wproj, proj_b, x, out, 1 | 2);
    // 5. h = LN2(out)
    ln_kernel<<<NROWS, 256>>>(out, ln2_g, ln2_b, h);
    // 6. ffh = relu(h @ ff1_w + ff1_b)  (bf16 out)
    bf16gemm_kernel<<<dim3(DFF / 128, NROWS / 128), 256, GEMM_SMEM_BYTES>>>(
        NROWS, DFF, DD, h, wff1, ff1_b, nullptr, ffh, 1 | 4 | 8);
    // 7. out += ffh @ ff2_w + ff2_b
    bf16gemm_kernel<<<dim3(DD / 128, NROWS / 128), 256, GEMM_SMEM_BYTES>>>(
        NROWS, DD, DFF, ffh, wff2, ff2_b, out, out, 1 | 2);
}

// round 15
// speedup vs baseline: 2.1168x; 1.1368x over previous
#include <cuda_runtime.h>
#include <cuda_bf16.h>
#include <math.h>
#include <stdint.h>

// ---------------- problem constants ----------------
#define BB 4
#define SS 2048
#define DD 1024
#define HH 16
#define HSZ 64
#define DFF 4096
#define NROWS (BB * SS)          // 8192
#define QKV_N (3 * DD)           // 3072

// ---------------- scratch (bf16 activations/weights) -----------------------
__device__ __nv_bfloat16 g_h[NROWS * DD];        // LN output
__device__ __nv_bfloat16 g_qkv[NROWS * QKV_N];   // Q|K|V head-concat
__device__ __nv_bfloat16 g_wqkv[QKV_N * DD];     // qkv weights T [n][d]
__device__ __nv_bfloat16 g_o[NROWS * DD];        // attention output
__device__ __nv_bfloat16 g_ffh[NROWS * DFF];     // FFN hidden
__device__ __nv_bfloat16 g_wproj[DD * DD];       // proj_w T [n][k]
__device__ __nv_bfloat16 g_wff1[DFF * DD];       // ff1_w T [n][k]
__device__ __nv_bfloat16 g_wff2[DD * DFF];       // ff2_w T [n][k]

// ==================== helpers ==============================================
__device__ __forceinline__ void mma_bf16(float* c, const uint32_t* a,
                                         const uint32_t* b) {
    asm volatile(
        "mma.sync.aligned.m16n8k16.row.col.f32.bf16.bf16.f32 "
        "{%0,%1,%2,%3}, {%4,%5,%6,%7}, {%8,%9}, {%0,%1,%2,%3};\n"
        : "+f"(c[0]), "+f"(c[1]), "+f"(c[2]), "+f"(c[3])
        : "r"(a[0]), "r"(a[1]), "r"(a[2]), "r"(a[3]),
          "r"(b[0]), "r"(b[1]));
}
__device__ __forceinline__ uint32_t s2u(const void* p) {
    return (uint32_t)__cvta_generic_to_shared(p);
}
__device__ __forceinline__ void cpasync16(uint32_t dst, const void* src) {
    asm volatile("cp.async.ca.shared.global [%0], [%1], 16;\n"
                 :: "r"(dst), "l"(src));
}
__device__ __forceinline__ uint32_t f2bfpair(float a, float b) {
    __nv_bfloat162 h = __floats2bfloat162_rn(a, b);
    return *reinterpret_cast<uint32_t*>(&h);
}
#define LDMX4(r0, r1, r2, r3, addr) \
    asm volatile("ldmatrix.sync.aligned.m8n8.x4.shared.b16 {%0,%1,%2,%3}, [%4];" \
                 : "=r"(r0), "=r"(r1), "=r"(r2), "=r"(r3) : "r"(addr))
#define LDMX4T(r0, r1, r2, r3, addr) \
    asm volatile("ldmatrix.sync.aligned.m8n8.x4.trans.shared.b16 {%0,%1,%2,%3}, [%4];" \
                 : "=r"(r0), "=r"(r1), "=r"(r2), "=r"(r3) : "r"(addr))

// ==================== weight prep ==========================================
__global__ void transpose_round_kernel(const float* __restrict__ src,
                                       __nv_bfloat16* __restrict__ dst,
                                       int K, int N)
{
    __shared__ float t[32][33];
    int n0 = blockIdx.x * 32, k0 = blockIdx.y * 32;
    int tx = threadIdx.x;
#pragma unroll
    for (int i = threadIdx.y; i < 32; i += 8)
        t[i][tx] = src[(size_t)(k0 + i) * N + n0 + tx];
    __syncthreads();
#pragma unroll
    for (int i = threadIdx.y; i < 32; i += 8)
        dst[(size_t)(n0 + i) * K + k0 + tx] = __float2bfloat16(t[tx][i]);
}

__global__ void repack_kernel(const float* __restrict__ wq,
                              const float* __restrict__ wk,
                              const float* __restrict__ wv,
                              __nv_bfloat16* __restrict__ WT)
{
    int idx = blockIdx.x * 256 + threadIdx.x;   // idx = n*DD + d
    if (idx >= DD * QKV_N) return;
    int d = idx & (DD - 1);
    int n = idx >> 10;
    int sel = n >> 10;
    int nn  = n & 1023;
    int hh  = nn >> 6;
    int e   = nn & 63;
    const float* src = (sel == 0) ? wq : (sel == 1) ? wk : wv;
    WT[idx] = __float2bfloat16(src[((size_t)hh * DD + d) * HSZ + e]);
}

// ==================== LayerNorm (bf16 output) ==============================
__global__ void ln_kernel(const float* __restrict__ in,
                          const float* __restrict__ gg,
                          const float* __restrict__ bb,
                          __nv_bfloat16* __restrict__ out)
{
    int row = blockIdx.x;
    const float* x = in + (size_t)row * DD;
    float v[4];
    float s = 0.f, s2 = 0.f;
#pragma unroll
    for (int k = 0; k < 4; k++) {
        v[k] = x[threadIdx.x + k * 256];
        s  += v[k];
        s2 += v[k] * v[k];
    }
#pragma unroll
    for (int off = 16; off; off >>= 1) {
        s  += __shfl_xor_sync(0xffffffffu, s,  off);
        s2 += __shfl_xor_sync(0xffffffffu, s2, off);
    }
    __shared__ float red[2][8];
    int wid = threadIdx.x >> 5, lane = threadIdx.x & 31;
    if (lane == 0) { red[0][wid] = s; red[1][wid] = s2; }
    __syncthreads();
    float S = 0.f, S2 = 0.f;
#pragma unroll
    for (int w = 0; w < 8; w++) { S += red[0][w]; S2 += red[1][w]; }
    float mean = S * (1.0f / DD);
    float var  = S2 * (1.0f / DD) - mean * mean;
    float rstd = rsqrtf(var + 1e-5f);
    __nv_bfloat16* o = out + (size_t)row * DD;
#pragma unroll
    for (int k = 0; k < 4; k++) {
        int c = threadIdx.x + k * 256;
        o[c] = __float2bfloat16((v[k] - mean) * rstd * gg[c] + bb[c]);
    }
}

// ==================== BF16 GEMM v2: ldmatrix + 3-stage cp.async ============
// C[M,N] = A[M,K] @ BT[N,K]^T. Tile 128x128x32, 8 warps (2x4 warp grid).
// Smem tile [128 rows][20 words]; A stages dsm[s*TW], B stages dsm[(3+s)*TW].
// flags: 1=+bias(f32), 2=+res(f32), 4=relu, 8=bf16 output (else f32)
#define TILE_WORDS (128 * 20)
#define GEMM_SMEM_BYTES (6 * TILE_WORDS * 4)   // 61440 B

__global__ __launch_bounds__(256, 2)
void bf16gemm_kernel(int M, int N, int K,
                     const __nv_bfloat16* __restrict__ A,
                     const __nv_bfloat16* __restrict__ BT,
                     const float* __restrict__ bias,
                     const float* __restrict__ res,
                     void* __restrict__ Cv,
                     int flags)
{
    extern __shared__ __align__(16) uint32_t dsm[];

    int tid  = threadIdx.x;
    int lane = tid & 31;
    int warp = tid >> 5;
    int g    = lane >> 2;
    int tig  = lane & 3;
    int warp_m = warp & 1;
    int warp_n = warp >> 1;
    int m0 = blockIdx.y * 128;
    int n0 = blockIdx.x * 128;

    float acc[4][4][4];
#pragma unroll
    for (int i = 0; i < 4; i++)
#pragma unroll
        for (int j = 0; j < 4; j++)
#pragma unroll
            for (int c = 0; c < 4; c++) acc[i][j][c] = 0.f;

    // ldmatrix per-lane offsets (in words)
    //  A x4: m0..m3 = (rows r..r+7,kw)(r+8..r+15,kw)(r..r+7,kw+4)(r+8..,kw+4)
    int arow_off = ((lane >> 3) & 1) * 8 + (lane & 7);
    int acol_off = (lane >> 4) * 4;
    //  B x4: m0..m3 = (rows n..n+7,kw)(n..n+7,kw+4)(n+8..n+15,kw)(n+8..,kw+4)
    int brow_off = ((lane >> 4) & 1) * 8 + (lane & 7);
    int bcol_off = ((lane >> 3) & 1) * 4;

    auto load_tiles = [&](int k0, int buf) {
        uint32_t* as = dsm + buf * TILE_WORDS;
        uint32_t* bs = dsm + (3 + buf) * TILE_WORDS;
#pragma unroll
        for (int q = 0; q < 2; q++) {
            int ch = q * 256 + tid;
            int rr = ch >> 2, cc = ch & 3;
            cpasync16(s2u(as + rr * 20 + cc * 4),
                      A + (size_t)(m0 + rr) * K + k0 + cc * 8);
        }
#pragma unroll
        for (int q = 0; q < 2; q++) {
            int ch = q * 256 + tid;
            int rr = ch >> 2, cc = ch & 3;
            cpasync16(s2u(bs + rr * 20 + cc * 4),
                      BT + (size_t)(n0 + rr) * K + k0 + cc * 8);
        }
    };

    int nk = K / 32;
    load_tiles(0, 0);
    asm volatile("cp.async.commit_group;\n");
    load_tiles(32, 1);
    asm volatile("cp.async.commit_group;\n");

    for (int kt = 0; kt < nk; kt++) {
        if (kt + 1 < nk)
            asm volatile("cp.async.wait_group 1;\n");
        else
            asm volatile("cp.async.wait_group 0;\n");
        __syncthreads();   // stage kt ready; all warps done computing kt-1

        if (kt + 2 < nk) {
            load_tiles((kt + 2) * 32, (kt + 2) % 3);
            asm volatile("cp.async.commit_group;\n");
        }

        int buf = kt % 3;
        const uint32_t* As = dsm + buf * TILE_WORDS;
        const uint32_t* Bs = dsm + (3 + buf) * TILE_WORDS;
#pragma unroll
        for (int s = 0; s < 2; s++) {
            int kw = s * 8;
            uint32_t afr[4][4], bfr[4][2];
#pragma unroll
            for (int i = 0; i < 4; i++) {
                int r = warp_m * 64 + i * 16;
                uint32_t addr = s2u(As + (r + arow_off) * 20 + kw + acol_off);
                LDMX4(afr[i][0], afr[i][1], afr[i][2], afr[i][3], addr);
            }
            {
                int nb = warp_n * 32;
                uint32_t r0, r1, r2, r3;
                uint32_t addr = s2u(Bs + (nb + brow_off) * 20 + kw + bcol_off);
                LDMX4(r0, r1, r2, r3, addr);
                bfr[0][0] = r0; bfr[0][1] = r1;
                bfr[1][0] = r2; bfr[1][1] = r3;
                addr = s2u(Bs + (nb + 16 + brow_off) * 20 + kw + bcol_off);
                LDMX4(r0, r1, r2, r3, addr);
                bfr[2][0] = r0; bfr[2][1] = r1;
                bfr[3][0] = r2; bfr[3][1] = r3;
            }
#pragma unroll
            for (int i = 0; i < 4; i++)
#pragma unroll
                for (int j = 0; j < 4; j++)
                    mma_bf16(acc[i][j], afr[i], bfr[j]);
        }
    }

    __syncthreads();   // all compute done before epilogue (no pending loads)

    bool outbf = (flags & 8) != 0;
#pragma unroll
    for (int j = 0; j < 4; j++) {
        int col = n0 + warp_n * 32 + j * 8 + 2 * tig;
        float b0 = 0.f, b1 = 0.f;
        if (flags & 1) { b0 = bias[col]; b1 = bias[col + 1]; }
#pragma unroll
        for (int i = 0; i < 4; i++) {
            int rr = m0 + warp_m * 64 + i * 16 + g;
#pragma unroll
            for (int half = 0; half < 2; half++) {
                int row = rr + half * 8;
                size_t base = (size_t)row * N + col;
                float v0 = acc[i][j][half * 2 + 0] + b0;
                float v1 = acc[i][j][half * 2 + 1] + b1;
                if (flags & 2) {
                    float2 rv = *(const float2*)(res + base);
                    v0 += rv.x; v1 += rv.y;
                }
                if (flags & 4) { v0 = fmaxf(v0, 0.f); v1 = fmaxf(v1, 0.f); }
                if (outbf) {
                    *(uint32_t*)((__nv_bfloat16*)Cv + base) = f2bfpair(v0, v1);
                } else {
                    *(float2*)((float*)Cv + base) = make_float2(v0, v1);
                }
            }
        }
    }
}

// ==================== Full-BF16 flash attention (round-13 winner) ==========
#define ATT_SMEM_BYTES ((128*36 + 128*36 + 64*36) * 4)   // 46080

__global__ __launch_bounds__(256, 2)
void attn_tc_kernel(const __nv_bfloat16* __restrict__ qkv,
                    __nv_bfloat16* __restrict__ O)
{
    extern __shared__ uint32_t sm[];
    uint32_t* Qs  = sm;                  // [128][36]
    uint32_t* KPs = sm + 128 * 36;       // Ks[64][36] / Ps[128][36]
    uint32_t* Vs  = sm + 256 * 36;       // [64][36]

    int b  = blockIdx.z;
    int h  = blockIdx.y;
    int q0 = blockIdx.x * 128;
    int tid  = threadIdx.x;
    int lane = tid & 31, warp = tid >> 5;
    int g    = lane >> 2, tig = lane & 3;

#pragma unroll
    for (int q = 0; q < 4; q++) {
        int ch = q * 256 + tid;
        int r = ch >> 3, c4 = ch & 7;
        *(uint4*)&Qs[r * 36 + c4 * 4] =
            *(const uint4*)(qkv + (size_t)(b * SS + q0 + r) * QKV_N + h * HSZ + c4 * 8);
    }

    float o_[8][4];
#pragma unroll
    for (int n = 0; n < 8; n++)
#pragma unroll
        for (int c = 0; c < 4; c++) o_[n][c] = 0.f;
    float m0 = -1e30f, m8 = -1e30f, l0 = 0.f, l8 = 0.f;

    int Rw   = q0 + warp * 16;
    int row0 = Rw + g;
    int rmax = Rw + 15;
    int rloc = warp * 16 + g;

    int vmrow_base = ((lane >> 3) & 1) * 8 + (lane & 7);
    int vnw = (lane >> 4) * 4;

    int ntile = 2 * blockIdx.x + 2;
    for (int jt = 0; jt < ntile; jt++) {
        int j0 = jt * 64;
        __syncthreads();
#pragma unroll
        for (int q = 0; q < 2; q++) {
            int ch = q * 256 + tid;
            int t = ch >> 3, c4 = ch & 7;
            const __nv_bfloat16* kp =
                qkv + (size_t)(b * SS + j0 + t) * QKV_N + DD + h * HSZ + c4 * 8;
            *(uint4*)&KPs[t * 36 + c4 * 4] = *(const uint4*)kp;
            *(uint4*)&Vs[t * 36 + c4 * 4]  = *(const uint4*)(kp + DD);
        }
        __syncthreads();

        bool active = (j0 <= rmax);
        float p[8][4];
        if (active) {
#pragma unroll
            for (int n = 0; n < 8; n++)
#pragma unroll
                for (int c = 0; c < 4; c++) p[n][c] = 0.f;
#pragma unroll
            for (int ks = 0; ks < 4; ks++) {
                int kw = ks * 8;
                uint32_t a[4];
                a[0] = Qs[rloc * 36 + kw + tig];
                a[1] = Qs[(rloc + 8) * 36 + kw + tig];
                a[2] = Qs[rloc * 36 + kw + tig + 4];
                a[3] = Qs[(rloc + 8) * 36 + kw + tig + 4];
#pragma unroll
                for (int n = 0; n < 8; n++) {
                    uint32_t bf[2];
                    bf[0] = KPs[(n * 8 + g) * 36 + kw + tig];
                    bf[1] = KPs[(n * 8 + g) * 36 + kw + tig + 4];
                    mma_bf16(p[n], a, bf);
                }
            }
            bool needmask = (j0 + 63 > Rw);
            float mt0 = -1e30f, mt8 = -1e30f;
#pragma unroll
            for (int n = 0; n < 8; n++) {
#pragma unroll
                for (int c = 0; c < 4; c++) {
                    float v = p[n][c] * 0.125f;
                    if (needmask) {
                        int col = j0 + n * 8 + 2 * tig + (c & 1);
                        int row = row0 + (c >> 1) * 8;
                        if (col > row) v = -1e30f;
                    }
                    p[n][c] = v;
                    if (c < 2) mt0 = fmaxf(mt0, v); else mt8 = fmaxf(mt8, v);
                }
            }
            mt0 = fmaxf(mt0, __shfl_xor_sync(0xffffffffu, mt0, 1));
            mt0 = fmaxf(mt0, __shfl_xor_sync(0xffffffffu, mt0, 2));
            mt8 = fmaxf(mt8, __shfl_xor_sync(0xffffffffu, mt8, 1));
            mt8 = fmaxf(mt8, __shfl_xor_sync(0xffffffffu, mt8, 2));
            float nm0 = fmaxf(m0, mt0), nm8 = fmaxf(m8, mt8);
            float al0 = __expf(m0 - nm0), al8 = __expf(m8 - nm8);
            m0 = nm0; m8 = nm8;
            float ps0 = 0.f, ps8 = 0.f;
#pragma unroll
            for (int n = 0; n < 8; n++) {
                p[n][0] = __expf(p[n][0] - nm0);
                p[n][1] = __expf(p[n][1] - nm0);
                p[n][2] = __expf(p[n][2] - nm8);
                p[n][3] = __expf(p[n][3] - nm8);
                ps0 += p[n][0] + p[n][1];
                ps8 += p[n][2] + p[n][3];
            }
            ps0 += __shfl_xor_sync(0xffffffffu, ps0, 1);
            ps0 += __shfl_xor_sync(0xffffffffu, ps0, 2);
            ps8 += __shfl_xor_sync(0xffffffffu, ps8, 1);
            ps8 += __shfl_xor_sync(0xffffffffu, ps8, 2);
            l0 = l0 * al0 + ps0;
            l8 = l8 * al8 + ps8;
#pragma unroll
            for (int n = 0; n < 8; n++) {
                o_[n][0] *= al0; o_[n][1] *= al0;
                o_[n][2] *= al8; o_[n][3] *= al8;
            }
        }
        __syncthreads();

        if (active) {
#pragma unroll
            for (int n = 0; n < 8; n++) {
                KPs[rloc * 36 + n * 4 + tig]       = f2bfpair(p[n][0], p[n][1]);
                KPs[(rloc + 8) * 36 + n * 4 + tig] = f2bfpair(p[n][2], p[n][3]);
            }
#pragma unroll
            for (int ks = 0; ks < 4; ks++) {
                int kw = ks * 8;
                uint32_t a[4];
                a[0] = KPs[rloc * 36 + kw + tig];
                a[1] = KPs[(rloc + 8) * 36 + kw + tig];
                a[2] = KPs[rloc * 36 + kw + tig + 4];
                a[3] = KPs[(rloc + 8) * 36 + kw + tig + 4];
                int mrow = ks * 16 + vmrow_base;
#pragma unroll
                for (int jp = 0; jp < 4; jp++) {
                    uint32_t r0, r1, r2, r3;
                    uint32_t addr = s2u(&Vs[mrow * 36 + jp * 8 + vnw]);
                    LDMX4T(r0, r1, r2, r3, addr);
                    uint32_t bfa[2] = {r0, r1}, bfb[2] = {r2, r3};
                    mma_bf16(o_[jp * 2],     a, bfa);
                    mma_bf16(o_[jp * 2 + 1], a, bfb);
                }
            }
        }
    }

    float inv0 = 1.0f / l0, inv8 = 1.0f / l8;
    size_t base0 = (size_t)(b * SS + q0 + rloc) * DD + h * HSZ;
    size_t base8 = base0 + 8 * DD;
#pragma unroll
    for (int n = 0; n < 8; n++) {
        int col = n * 8 + 2 * tig;
        *(uint32_t*)(O + base0 + col) = f2bfpair(o_[n][0] * inv0, o_[n][1] * inv0);
        *(uint32_t*)(O + base8 + col) = f2bfpair(o_[n][2] * inv8, o_[n][3] * inv8);
    }
}

// ==================== host launcher ========================================
extern "C" void kernel_launch(void* const* d_in, const int* in_sizes, int n_in,
                              void* d_out, int out_size)
{
    const float* x      = (const float*)d_in[0];
    const float* wq     = (const float*)d_in[1];
    const float* wk     = (const float*)d_in[2];
    const float* wv     = (const float*)d_in[3];
    const float* proj_w = (const float*)d_in[4];
    const float* proj_b = (const float*)d_in[5];
    const float* ff1_w  = (const float*)d_in[6];
    const float* ff1_b  = (const float*)d_in[7];
    const float* ff2_w  = (const float*)d_in[8];
    const float* ff2_b  = (const float*)d_in[9];
    const float* ln1_g  = (const float*)d_in[10];
    const float* ln1_b  = (const float*)d_in[11];
    const float* ln2_g  = (const float*)d_in[12];
    const float* ln2_b  = (const float*)d_in[13];
    float* out = (float*)d_out;

    static __nv_bfloat16 *h = nullptr, *qkv, *wpack, *o, *ffh,
                         *wproj, *wff1, *wff2;
    if (!h) {
        cudaGetSymbolAddress((void**)&h,     g_h);
        cudaGetSymbolAddress((void**)&qkv,   g_qkv);
        cudaGetSymbolAddress((void**)&wpack, g_wqkv);
        cudaGetSymbolAddress((void**)&o,     g_o);
        cudaGetSymbolAddress((void**)&ffh,   g_ffh);
        cudaGetSymbolAddress((void**)&wproj, g_wproj);
        cudaGetSymbolAddress((void**)&wff1,  g_wff1);
        cudaGetSymbolAddress((void**)&wff2,  g_wff2);
        cudaFuncSetAttribute(attn_tc_kernel,
                             cudaFuncAttributeMaxDynamicSharedMemorySize,
                             ATT_SMEM_BYTES);
        cudaFuncSetAttribute(bf16gemm_kernel,
                             cudaFuncAttributeMaxDynamicSharedMemorySize,
                             GEMM_SMEM_BYTES);
    }

    // 0. weight prep
    repack_kernel<<<(DD * QKV_N + 255) / 256, 256>>>(wq, wk, wv, wpack);
    transpose_round_kernel<<<dim3(DD / 32, DD / 32),  dim3(32, 8)>>>(proj_w, wproj, DD,  DD);
    transpose_round_kernel<<<dim3(DFF / 32, DD / 32), dim3(32, 8)>>>(ff1_w,  wff1,  DD,  DFF);
    transpose_round_kernel<<<dim3(DD / 32, DFF / 32), dim3(32, 8)>>>(ff2_w,  wff2,  DFF, DD);
    // 1. h = LN1(x)
    ln_kernel<<<NROWS, 256>>>(x, ln1_g, ln1_b, h);
    // 2. qkv = h @ Wqkv  (bf16 out)
    bf16gemm_kernel<<<dim3(QKV_N / 128, NROWS / 128), 256, GEMM_SMEM_BYTES>>>(
        NROWS, QKV_N, DD, h, wpack, nullptr, nullptr, qkv, 8);
    // 3. flash attention -> o (bf16)
    attn_tc_kernel<<<dim3(SS / 128, HH, BB), 256, ATT_SMEM_BYTES>>>(qkv, o);
    // 4. out = x + o @ proj_w + proj_b
    bf16gemm_kernel<<<dim3(DD / 128, NROWS / 128), 256, GEMM_SMEM_BYTES>>>(
        NROWS, DD, DD, o, wproj, proj_b, x, out, 1 | 2);
    // 5. h = LN2(out)
    ln_kernel<<<NROWS, 256>>>(out, ln2_g, ln2_b, h);
    // 6. ffh = relu(h @ ff1_w + ff1_b)  (bf16 out)
    bf16gemm_kernel<<<dim3(DFF / 128, NROWS / 128), 256, GEMM_SMEM_BYTES>>>(
        NROWS, DFF, DD, h, wff1, ff1_b, nullptr, ffh, 1 | 4 | 8);
    // 7. out += ffh @ ff2_w + ff2_b
    bf16gemm_kernel<<<dim3(DD / 128, NROWS / 128), 256, GEMM_SMEM_BYTES>>>(
        NROWS, DD, DFF, ffh, wff2, ff2_b, out, out, 1 | 2);
}

// round 16
// speedup vs baseline: 2.1350x; 1.0086x over previous
#include <cuda_runtime.h>
#include <cuda_bf16.h>
#include <math.h>
#include <stdint.h>

// ---------------- problem constants ----------------
#define BB 4
#define SS 2048
#define DD 1024
#define HH 16
#define HSZ 64
#define DFF 4096
#define NROWS (BB * SS)          // 8192
#define QKV_N (3 * DD)           // 3072

// ---------------- scratch (bf16 activations/weights) -----------------------
__device__ __nv_bfloat16 g_h[NROWS * DD];        // LN output
__device__ __nv_bfloat16 g_qkv[NROWS * QKV_N];   // Q|K|V head-concat
__device__ __nv_bfloat16 g_wqkv[QKV_N * DD];     // qkv weights T [n][d]
__device__ __nv_bfloat16 g_o[NROWS * DD];        // attention output
__device__ __nv_bfloat16 g_ffh[NROWS * DFF];     // FFN hidden
__device__ __nv_bfloat16 g_wproj[DD * DD];       // proj_w T [n][k]
__device__ __nv_bfloat16 g_wff1[DFF * DD];       // ff1_w T [n][k]
__device__ __nv_bfloat16 g_wff2[DD * DFF];       // ff2_w T [n][k]

// ==================== helpers ==============================================
__device__ __forceinline__ void mma_bf16(float* c, const uint32_t* a,
                                         const uint32_t* b) {
    asm volatile(
        "mma.sync.aligned.m16n8k16.row.col.f32.bf16.bf16.f32 "
        "{%0,%1,%2,%3}, {%4,%5,%6,%7}, {%8,%9}, {%0,%1,%2,%3};\n"
        : "+f"(c[0]), "+f"(c[1]), "+f"(c[2]), "+f"(c[3])
        : "r"(a[0]), "r"(a[1]), "r"(a[2]), "r"(a[3]),
          "r"(b[0]), "r"(b[1]));
}
__device__ __forceinline__ uint32_t s2u(const void* p) {
    return (uint32_t)__cvta_generic_to_shared(p);
}
__device__ __forceinline__ void cpasync16(uint32_t dst, const void* src) {
    asm volatile("cp.async.ca.shared.global [%0], [%1], 16;\n"
                 :: "r"(dst), "l"(src));
}
__device__ __forceinline__ uint32_t f2bfpair(float a, float b) {
    __nv_bfloat162 h = __floats2bfloat162_rn(a, b);
    return *reinterpret_cast<uint32_t*>(&h);
}
#define LDMX4(r0, r1, r2, r3, addr) \
    asm volatile("ldmatrix.sync.aligned.m8n8.x4.shared.b16 {%0,%1,%2,%3}, [%4];" \
                 : "=r"(r0), "=r"(r1), "=r"(r2), "=r"(r3) : "r"(addr))
#define LDMX4T(r0, r1, r2, r3, addr) \
    asm volatile("ldmatrix.sync.aligned.m8n8.x4.trans.shared.b16 {%0,%1,%2,%3}, [%4];" \
                 : "=r"(r0), "=r"(r1), "=r"(r2), "=r"(r3) : "r"(addr))

// ==================== weight prep ==========================================
// dst[n][k] = bf16(src[k][n]); tile: 64 k-rows x 32 n-cols; packed u32 stores.
__global__ void transpose_round_kernel(const float* __restrict__ src,
                                       __nv_bfloat16* __restrict__ dst,
                                       int K, int N)
{
    __shared__ float t[64][33];
    int n0 = blockIdx.x * 32, k0 = blockIdx.y * 64;
    int tx = threadIdx.x;
#pragma unroll
    for (int j = threadIdx.y; j < 64; j += 8)
        t[j][tx] = src[(size_t)(k0 + j) * N + n0 + tx];
    __syncthreads();
#pragma unroll
    for (int i = threadIdx.y; i < 32; i += 8) {
        uint32_t w = f2bfpair(t[2 * tx][i], t[2 * tx + 1][i]);
        *(uint32_t*)&dst[(size_t)(n0 + i) * K + k0 + 2 * tx] = w;
    }
}

// qkv repack: WT[n][d] = bf16(src_sel[(hh*DD+d)*HSZ+e]),  n = sel*1024+hh*64+e
// per (sel,hh): 1024(d) x 64(e) transpose; tile 64 d-rows x 32 e-cols.
__global__ void repack_kernel(const float* __restrict__ wq,
                              const float* __restrict__ wk,
                              const float* __restrict__ wv,
                              __nv_bfloat16* __restrict__ WT)
{
    __shared__ float t[64][33];
    int head = blockIdx.z;            // 0..47 = sel*16 + hh
    int sel = head >> 4, hh = head & 15;
    int d0 = blockIdx.x * 64;         // 16 tiles
    int e0 = blockIdx.y * 32;         // 2 tiles
    int tx = threadIdx.x;
    const float* src = (sel == 0) ? wq : (sel == 1) ? wk : wv;
    const float* base = src + ((size_t)hh * DD) * HSZ;
#pragma unroll
    for (int j = threadIdx.y; j < 64; j += 8)
        t[j][tx] = base[(size_t)(d0 + j) * HSZ + e0 + tx];
    __syncthreads();
    int n0 = sel * 1024 + hh * 64 + e0;
#pragma unroll
    for (int i = threadIdx.y; i < 32; i += 8) {
        uint32_t w = f2bfpair(t[2 * tx][i], t[2 * tx + 1][i]);
        *(uint32_t*)&WT[(size_t)(n0 + i) * DD + d0 + 2 * tx] = w;
    }
}

// ==================== LayerNorm (float4 loads, packed bf16 stores) =========
__global__ void ln_kernel(const float* __restrict__ in,
                          const float* __restrict__ gg,
                          const float* __restrict__ bb,
                          __nv_bfloat16* __restrict__ out)
{
    int row = blockIdx.x;
    int c0 = threadIdx.x * 4;
    float4 v = *(const float4*)(in + (size_t)row * DD + c0);
    float s  = v.x + v.y + v.z + v.w;
    float s2 = v.x * v.x + v.y * v.y + v.z * v.z + v.w * v.w;
#pragma unroll
    for (int off = 16; off; off >>= 1) {
        s  += __shfl_xor_sync(0xffffffffu, s,  off);
        s2 += __shfl_xor_sync(0xffffffffu, s2, off);
    }
    __shared__ float red[2][8];
    int wid = threadIdx.x >> 5, lane = threadIdx.x & 31;
    if (lane == 0) { red[0][wid] = s; red[1][wid] = s2; }
    __syncthreads();
    float S = 0.f, S2 = 0.f;
#pragma unroll
    for (int w = 0; w < 8; w++) { S += red[0][w]; S2 += red[1][w]; }
    float mean = S * (1.0f / DD);
    float var  = S2 * (1.0f / DD) - mean * mean;
    float rstd = rsqrtf(var + 1e-5f);
    float4 gv = *(const float4*)(gg + c0);
    float4 bv = *(const float4*)(bb + c0);
    uint2 o;
    o.x = f2bfpair((v.x - mean) * rstd * gv.x + bv.x,
                   (v.y - mean) * rstd * gv.y + bv.y);
    o.y = f2bfpair((v.z - mean) * rstd * gv.z + bv.z,
                   (v.w - mean) * rstd * gv.w + bv.w);
    *(uint2*)(out + (size_t)row * DD + c0) = o;
}

// ==================== BF16 GEMM v2: ldmatrix + 3-stage cp.async ============
#define TILE_WORDS (128 * 20)
#define GEMM_SMEM_BYTES (6 * TILE_WORDS * 4)   // 61440 B

__global__ __launch_bounds__(256, 2)
void bf16gemm_kernel(int M, int N, int K,
                     const __nv_bfloat16* __restrict__ A,
                     const __nv_bfloat16* __restrict__ BT,
                     const float* __restrict__ bias,
                     const float* __restrict__ res,
                     void* __restrict__ Cv,
                     int flags)
{
    extern __shared__ __align__(16) uint32_t dsm[];

    int tid  = threadIdx.x;
    int lane = tid & 31;
    int warp = tid >> 5;
    int g    = lane >> 2;
    int tig  = lane & 3;
    int warp_m = warp & 1;
    int warp_n = warp >> 1;
    int m0 = blockIdx.y * 128;
    int n0 = blockIdx.x * 128;

    float acc[4][4][4];
#pragma unroll
    for (int i = 0; i < 4; i++)
#pragma unroll
        for (int j = 0; j < 4; j++)
#pragma unroll
            for (int c = 0; c < 4; c++) acc[i][j][c] = 0.f;

    int arow_off = ((lane >> 3) & 1) * 8 + (lane & 7);
    int acol_off = (lane >> 4) * 4;
    int brow_off = ((lane >> 4) & 1) * 8 + (lane & 7);
    int bcol_off = ((lane >> 3) & 1) * 4;

    auto load_tiles = [&](int k0, int buf) {
        uint32_t* as = dsm + buf * TILE_WORDS;
        uint32_t* bs = dsm + (3 + buf) * TILE_WORDS;
#pragma unroll
        for (int q = 0; q < 2; q++) {
            int ch = q * 256 + tid;
            int rr = ch >> 2, cc = ch & 3;
            cpasync16(s2u(as + rr * 20 + cc * 4),
                      A + (size_t)(m0 + rr) * K + k0 + cc * 8);
        }
#pragma unroll
        for (int q = 0; q < 2; q++) {
            int ch = q * 256 + tid;
            int rr = ch >> 2, cc = ch & 3;
            cpasync16(s2u(bs + rr * 20 + cc * 4),
                      BT + (size_t)(n0 + rr) * K + k0 + cc * 8);
        }
    };

    int nk = K / 32;
    load_tiles(0, 0);
    asm volatile("cp.async.commit_group;\n");
    load_tiles(32, 1);
    asm volatile("cp.async.commit_group;\n");

    for (int kt = 0; kt < nk; kt++) {
        if (kt + 1 < nk)
            asm volatile("cp.async.wait_group 1;\n");
        else
            asm volatile("cp.async.wait_group 0;\n");
        __syncthreads();   // stage kt ready; all warps done computing kt-1

        if (kt + 2 < nk) {
            load_tiles((kt + 2) * 32, (kt + 2) % 3);
            asm volatile("cp.async.commit_group;\n");
        }

        int buf = kt % 3;
        const uint32_t* As = dsm + buf * TILE_WORDS;
        const uint32_t* Bs = dsm + (3 + buf) * TILE_WORDS;
#pragma unroll
        for (int s = 0; s < 2; s++) {
            int kw = s * 8;
            uint32_t afr[4][4], bfr[4][2];
#pragma unroll
            for (int i = 0; i < 4; i++) {
                int r = warp_m * 64 + i * 16;
                uint32_t addr = s2u(As + (r + arow_off) * 20 + kw + acol_off);
                LDMX4(afr[i][0], afr[i][1], afr[i][2], afr[i][3], addr);
            }
            {
                int nb = warp_n * 32;
                uint32_t r0, r1, r2, r3;
                uint32_t addr = s2u(Bs + (nb + brow_off) * 20 + kw + bcol_off);
                LDMX4(r0, r1, r2, r3, addr);
                bfr[0][0] = r0; bfr[0][1] = r1;
                bfr[1][0] = r2; bfr[1][1] = r3;
                addr = s2u(Bs + (nb + 16 + brow_off) * 20 + kw + bcol_off);
                LDMX4(r0, r1, r2, r3, addr);
                bfr[2][0] = r0; bfr[2][1] = r1;
                bfr[3][0] = r2; bfr[3][1] = r3;
            }
#pragma unroll
            for (int i = 0; i < 4; i++)
#pragma unroll
                for (int j = 0; j < 4; j++)
                    mma_bf16(acc[i][j], afr[i], bfr[j]);
        }
    }

    // epilogue uses no smem; no barrier needed
    bool outbf = (flags & 8) != 0;
#pragma unroll
    for (int j = 0; j < 4; j++) {
        int col = n0 + warp_n * 32 + j * 8 + 2 * tig;
        float b0 = 0.f, b1 = 0.f;
        if (flags & 1) { b0 = bias[col]; b1 = bias[col + 1]; }
#pragma unroll
        for (int i = 0; i < 4; i++) {
            int rr = m0 + warp_m * 64 + i * 16 + g;
#pragma unroll
            for (int half = 0; half < 2; half++) {
                int row = rr + half * 8;
                size_t base = (size_t)row * N + col;
                float v0 = acc[i][j][half * 2 + 0] + b0;
                float v1 = acc[i][j][half * 2 + 1] + b1;
                if (flags & 2) {
                    float2 rv = *(const float2*)(res + base);
                    v0 += rv.x; v1 += rv.y;
                }
                if (flags & 4) { v0 = fmaxf(v0, 0.f); v1 = fmaxf(v1, 0.f); }
                if (outbf) {
                    *(uint32_t*)((__nv_bfloat16*)Cv + base) = f2bfpair(v0, v1);
                } else {
                    *(float2*)((float*)Cv + base) = make_float2(v0, v1);
                }
            }
        }
    }
}

// ==================== Full-BF16 flash attention (round-14 winner) ==========
#define ATT_SMEM_BYTES ((128*36 + 128*36 + 64*36) * 4)   // 46080

__global__ __launch_bounds__(256, 2)
void attn_tc_kernel(const __nv_bfloat16* __restrict__ qkv,
                    __nv_bfloat16* __restrict__ O)
{
    extern __shared__ uint32_t sm[];
    uint32_t* Qs  = sm;                  // [128][36]
    uint32_t* KPs = sm + 128 * 36;       // Ks[64][36] / Ps[128][36]
    uint32_t* Vs  = sm + 256 * 36;       // [64][36]

    int b  = blockIdx.z;
    int h  = blockIdx.y;
    int q0 = blockIdx.x * 128;
    int tid  = threadIdx.x;
    int lane = tid & 31, warp = tid >> 5;
    int g    = lane >> 2, tig = lane & 3;

#pragma unroll
    for (int q = 0; q < 4; q++) {
        int ch = q * 256 + tid;
        int r = ch >> 3, c4 = ch & 7;
        *(uint4*)&Qs[r * 36 + c4 * 4] =
            *(const uint4*)(qkv + (size_t)(b * SS + q0 + r) * QKV_N + h * HSZ + c4 * 8);
    }

    float o_[8][4];
#pragma unroll
    for (int n = 0; n < 8; n++)
#pragma unroll
        for (int c = 0; c < 4; c++) o_[n][c] = 0.f;
    float m0 = -1e30f, m8 = -1e30f, l0 = 0.f, l8 = 0.f;

    int Rw   = q0 + warp * 16;
    int row0 = Rw + g;
    int rmax = Rw + 15;
    int rloc = warp * 16 + g;

    int vmrow_base = ((lane >> 3) & 1) * 8 + (lane & 7);
    int vnw = (lane >> 4) * 4;

    int ntile = 2 * blockIdx.x + 2;
    for (int jt = 0; jt < ntile; jt++) {
        int j0 = jt * 64;
        __syncthreads();
#pragma unroll
        for (int q = 0; q < 2; q++) {
            int ch = q * 256 + tid;
            int t = ch >> 3, c4 = ch & 7;
            const __nv_bfloat16* kp =
                qkv + (size_t)(b * SS + j0 + t) * QKV_N + DD + h * HSZ + c4 * 8;
            *(uint4*)&KPs[t * 36 + c4 * 4] = *(const uint4*)kp;
            *(uint4*)&Vs[t * 36 + c4 * 4]  = *(const uint4*)(kp + DD);
        }
        __syncthreads();

        bool active = (j0 <= rmax);
        float p[8][4];
        if (active) {
#pragma unroll
            for (int n = 0; n < 8; n++)
#pragma unroll
                for (int c = 0; c < 4; c++) p[n][c] = 0.f;
#pragma unroll
            for (int ks = 0; ks < 4; ks++) {
                int kw = ks * 8;
                uint32_t a[4];
                a[0] = Qs[rloc * 36 + kw + tig];
                a[1] = Qs[(rloc + 8) * 36 + kw + tig];
                a[2] = Qs[rloc * 36 + kw + tig + 4];
                a[3] = Qs[(rloc + 8) * 36 + kw + tig + 4];
#pragma unroll
                for (int n = 0; n < 8; n++) {
                    uint32_t bf[2];
                    bf[0] = KPs[(n * 8 + g) * 36 + kw + tig];
                    bf[1] = KPs[(n * 8 + g) * 36 + kw + tig + 4];
                    mma_bf16(p[n], a, bf);
                }
            }
            bool needmask = (j0 + 63 > Rw);
            float mt0 = -1e30f, mt8 = -1e30f;
#pragma unroll
            for (int n = 0; n < 8; n++) {
#pragma unroll
                for (int c = 0; c < 4; c++) {
                    float v = p[n][c] * 0.125f;
                    if (needmask) {
                        int col = j0 + n * 8 + 2 * tig + (c & 1);
                        int row = row0 + (c >> 1) * 8;
                        if (col > row) v = -1e30f;
                    }
                    p[n][c] = v;
                    if (c < 2) mt0 = fmaxf(mt0, v); else mt8 = fmaxf(mt8, v);
                }
            }
            mt0 = fmaxf(mt0, __shfl_xor_sync(0xffffffffu, mt0, 1));
            mt0 = fmaxf(mt0, __shfl_xor_sync(0xffffffffu, mt0, 2));
            mt8 = fmaxf(mt8, __shfl_xor_sync(0xffffffffu, mt8, 1));
            mt8 = fmaxf(mt8, __shfl_xor_sync(0xffffffffu, mt8, 2));
            float nm0 = fmaxf(m0, mt0), nm8 = fmaxf(m8, mt8);
            float al0 = __expf(m0 - nm0), al8 = __expf(m8 - nm8);
            m0 = nm0; m8 = nm8;
            float ps0 = 0.f, ps8 = 0.f;
#pragma unroll
            for (int n = 0; n < 8; n++) {
                p[n][0] = __expf(p[n][0] - nm0);
                p[n][1] = __expf(p[n][1] - nm0);
                p[n][2] = __expf(p[n][2] - nm8);
                p[n][3] = __expf(p[n][3] - nm8);
                ps0 += p[n][0] + p[n][1];
                ps8 += p[n][2] + p[n][3];
            }
            ps0 += __shfl_xor_sync(0xffffffffu, ps0, 1);
            ps0 += __shfl_xor_sync(0xffffffffu, ps0, 2);
            ps8 += __shfl_xor_sync(0xffffffffu, ps8, 1);
            ps8 += __shfl_xor_sync(0xffffffffu, ps8, 2);
            l0 = l0 * al0 + ps0;
            l8 = l8 * al8 + ps8;
#pragma unroll
            for (int n = 0; n < 8; n++) {
                o_[n][0] *= al0; o_[n][1] *= al0;
                o_[n][2] *= al8; o_[n][3] *= al8;
            }
        }
        __syncthreads();

        if (active) {
#pragma unroll
            for (int n = 0; n < 8; n++) {
                KPs[rloc * 36 + n * 4 + tig]       = f2bfpair(p[n][0], p[n][1]);
                KPs[(rloc + 8) * 36 + n * 4 + tig] = f2bfpair(p[n][2], p[n][3]);
            }
#pragma unroll
            for (int ks = 0; ks < 4; ks++) {
                int kw = ks * 8;
                uint32_t a[4];
                a[0] = KPs[rloc * 36 + kw + tig];
                a[1] = KPs[(rloc + 8) * 36 + kw + tig];
                a[2] = KPs[rloc * 36 + kw + tig + 4];
                a[3] = KPs[(rloc + 8) * 36 + kw + tig + 4];
                int mrow = ks * 16 + vmrow_base;
#pragma unroll
                for (int jp = 0; jp < 4; jp++) {
                    uint32_t r0, r1, r2, r3;
                    uint32_t addr = s2u(&Vs[mrow * 36 + jp * 8 + vnw]);
                    LDMX4T(r0, r1, r2, r3, addr);
                    uint32_t bfa[2] = {r0, r1}, bfb[2] = {r2, r3};
                    mma_bf16(o_[jp * 2],     a, bfa);
                    mma_bf16(o_[jp * 2 + 1], a, bfb);
                }
            }
        }
    }

    float inv0 = 1.0f / l0, inv8 = 1.0f / l8;
    size_t base0 = (size_t)(b * SS + q0 + rloc) * DD + h * HSZ;
    size_t base8 = base0 + 8 * DD;
#pragma unroll
    for (int n = 0; n < 8; n++) {
        int col = n * 8 + 2 * tig;
        *(uint32_t*)(O + base0 + col) = f2bfpair(o_[n][0] * inv0, o_[n][1] * inv0);
        *(uint32_t*)(O + base8 + col) = f2bfpair(o_[n][2] * inv8, o_[n][3] * inv8);
    }
}

// ==================== host launcher ========================================
extern "C" void kernel_launch(void* const* d_in, const int* in_sizes, int n_in,
                              void* d_out, int out_size)
{
    const float* x      = (const float*)d_in[0];
    const float* wq     = (const float*)d_in[1];
    const float* wk     = (const float*)d_in[2];
    const float* wv     = (const float*)d_in[3];
    const float* proj_w = (const float*)d_in[4];
    const float* proj_b = (const float*)d_in[5];
    const float* ff1_w  = (const float*)d_in[6];
    const float* ff1_b  = (const float*)d_in[7];
    const float* ff2_w  = (const float*)d_in[8];
    const float* ff2_b  = (const float*)d_in[9];
    const float* ln1_g  = (const float*)d_in[10];
    const float* ln1_b  = (const float*)d_in[11];
    const float* ln2_g  = (const float*)d_in[12];
    const float* ln2_b  = (const float*)d_in[13];
    float* out = (float*)d_out;

    static __nv_bfloat16 *h = nullptr, *qkv, *wpack, *o, *ffh,
                         *wproj, *wff1, *wff2;
    if (!h) {
        cudaGetSymbolAddress((void**)&h,     g_h);
        cudaGetSymbolAddress((void**)&qkv,   g_qkv);
        cudaGetSymbolAddress((void**)&wpack, g_wqkv);
        cudaGetSymbolAddress((void**)&o,     g_o);
        cudaGetSymbolAddress((void**)&ffh,   g_ffh);
        cudaGetSymbolAddress((void**)&wproj, g_wproj);
        cudaGetSymbolAddress((void**)&wff1,  g_wff1);
        cudaGetSymbolAddress((void**)&wff2,  g_wff2);
        cudaFuncSetAttribute(attn_tc_kernel,
                             cudaFuncAttributeMaxDynamicSharedMemorySize,
                             ATT_SMEM_BYTES);
        cudaFuncSetAttribute(bf16gemm_kernel,
                             cudaFuncAttributeMaxDynamicSharedMemorySize,
                             GEMM_SMEM_BYTES);
    }

    // 0. weight prep (coalesced tiled transposes, packed bf16 stores)
    repack_kernel<<<dim3(DD / 64, HSZ / 32, 48), dim3(32, 8)>>>(wq, wk, wv, wpack);
    transpose_round_kernel<<<dim3(DD / 32, DD / 64),  dim3(32, 8)>>>(proj_w, wproj, DD,  DD);
    transpose_round_kernel<<<dim3(DFF / 32, DD / 64), dim3(32, 8)>>>(ff1_w,  wff1,  DD,  DFF);
    transpose_round_kernel<<<dim3(DD / 32, DFF / 64), dim3(32, 8)>>>(ff2_w,  wff2,  DFF, DD);
    // 1. h = LN1(x)
    ln_kernel<<<NROWS, 256>>>(x, ln1_g, ln1_b, h);
    // 2. qkv = h @ Wqkv  (bf16 out)
    bf16gemm_kernel<<<dim3(QKV_N / 128, NROWS / 128), 256, GEMM_SMEM_BYTES>>>(
        NROWS, QKV_N, DD, h, wpack, nullptr, nullptr, qkv, 8);
    // 3. flash attention -> o (bf16)
    attn_tc_kernel<<<dim3(SS / 128, HH, BB), 256, ATT_SMEM_BYTES>>>(qkv, o);
    // 4. out = x + o @ proj_w + proj_b
    bf16gemm_kernel<<<dim3(DD / 128, NROWS / 128), 256, GEMM_SMEM_BYTES>>>(
        NROWS, DD, DD, o, wproj, proj_b, x, out, 1 | 2);
    // 5. h = LN2(out)
    ln_kernel<<<NROWS, 256>>>(out, ln2_g, ln2_b, h);
    // 6. ffh = relu(h @ ff1_w + ff1_b)  (bf16 out)
    bf16gemm_kernel<<<dim3(DFF / 128, NROWS / 128), 256, GEMM_SMEM_BYTES>>>(
        NROWS, DFF, DD, h, wff1, ff1_b, nullptr, ffh, 1 | 4 | 8);
    // 7. out += ffh @ ff2_w + ff2_b
    bf16gemm_kernel<<<dim3(DD / 128, NROWS / 128), 256, GEMM_SMEM_BYTES>>>(
        NROWS, DD, DFF, ffh, wff2, ff2_b, out, out, 1 | 2);
}